// round 2
// baseline (speedup 1.0000x reference)
#include <cuda_runtime.h>
#include <math.h>
#include <stddef.h>

#define NN 100000
#define DD 256
#define RR 4
#define TT 150000
#define HH 2

constexpr size_t ND  = (size_t)NN * DD;         // 25.6M floats
constexpr size_t RND = (size_t)RR * NN * DD;    // 102.4M floats

// ---- single scratch arena (2.05 GB) with lifetime-based aliasing ----
// [0, RND)        : src  -> later x1 (in-place LN)
// [RND, 4*RND)    : phase-A scratch (xres,u,glog,nmsg,tmsg,cnt) -> qkv -> oproj -> ff1
// [4*RND, 5*RND)  : oattn -> ff2
__device__ float g_arena[5 * RND];
__device__ float g_comb[(size_t)RR * DD * DD];

// ---------------- helpers ----------------------------------------------------
__device__ __forceinline__ float warp_sum(float v) {
#pragma unroll
    for (int o = 16; o; o >>= 1) v += __shfl_xor_sync(0xffffffffu, v, o);
    return v;
}
__device__ __forceinline__ float gelu_exact(float x) {
    return 0.5f * x * (1.0f + erff(x * 0.7071067811865475f));
}

// ---------------- SGEMM: C[M,Nc] = A[M,K] @ B[Nc,K]^T  (+bias/+gelu/+accum) ---
// TRIA: A rows are gathered means of 3 x-rows per triangle index.
#define BM 128
#define BN 128
#define BK 16

template <int TRIA, int ACT, int ACCUM>
__global__ __launch_bounds__(256)
void sgemm_kernel(const float* __restrict__ A, const float* __restrict__ B,
                  float* __restrict__ C, const float* __restrict__ bias,
                  const int* __restrict__ tri, int triN,
                  int M, int Ncols, int K, int lda, int ldb, int ldc)
{
    __shared__ float As[BK][BM];
    __shared__ float Bs[BK][BN];
    const int t  = threadIdx.x;
    const int m0 = blockIdx.x * BM;
    const int n0 = blockIdx.y * BN;
    const int w = t >> 5, lane = t & 31;
    const int wm = w & 3, wn = w >> 2;       // 4 warps along M, 2 along N
    const int lm = lane & 3, ln = lane >> 2; // 4 x 8 lanes
    const int tm = wm * 32 + lm * 8;
    const int tn = wn * 64 + ln * 8;

    float acc[8][8];
#pragma unroll
    for (int i = 0; i < 8; i++)
#pragma unroll
        for (int j = 0; j < 8; j++) acc[i][j] = 0.f;

    for (int kk = 0; kk < K; kk += BK) {
        // --- load A tile (128x16) : 512 float4, 2 per thread ---
#pragma unroll
        for (int qd = 0; qd < 2; qd++) {
            int idx = t + qd * 256;
            int row = idx >> 2;
            int kq  = (idx & 3) << 2;
            float4 va = make_float4(0.f, 0.f, 0.f, 0.f);
            int gr = m0 + row;
            if (gr < M) {
                if (TRIA) {
                    int i0 = tri[gr], i1 = tri[triN + gr], i2 = tri[2 * triN + gr];
                    float4 a0 = *(const float4*)(A + (size_t)i0 * lda + kk + kq);
                    float4 a1 = *(const float4*)(A + (size_t)i1 * lda + kk + kq);
                    float4 a2 = *(const float4*)(A + (size_t)i2 * lda + kk + kq);
                    const float third = 1.f / 3.f;
                    va.x = (a0.x + a1.x + a2.x) * third;
                    va.y = (a0.y + a1.y + a2.y) * third;
                    va.z = (a0.z + a1.z + a2.z) * third;
                    va.w = (a0.w + a1.w + a2.w) * third;
                } else {
                    va = *(const float4*)(A + (size_t)gr * lda + kk + kq);
                }
            }
            As[kq + 0][row] = va.x; As[kq + 1][row] = va.y;
            As[kq + 2][row] = va.z; As[kq + 3][row] = va.w;
        }
        // --- load B tile (128x16); Ncols is always a multiple of 128 here ---
#pragma unroll
        for (int qd = 0; qd < 2; qd++) {
            int idx = t + qd * 256;
            int row = idx >> 2;
            int kq  = (idx & 3) << 2;
            float4 vb = *(const float4*)(B + (size_t)(n0 + row) * ldb + kk + kq);
            Bs[kq + 0][row] = vb.x; Bs[kq + 1][row] = vb.y;
            Bs[kq + 2][row] = vb.z; Bs[kq + 3][row] = vb.w;
        }
        __syncthreads();
#pragma unroll
        for (int k = 0; k < BK; k++) {
            float4 a0 = *(const float4*)&As[k][tm];
            float4 a1 = *(const float4*)&As[k][tm + 4];
            float4 b0 = *(const float4*)&Bs[k][tn];
            float4 b1 = *(const float4*)&Bs[k][tn + 4];
            float av[8] = {a0.x, a0.y, a0.z, a0.w, a1.x, a1.y, a1.z, a1.w};
            float bv[8] = {b0.x, b0.y, b0.z, b0.w, b1.x, b1.y, b1.z, b1.w};
#pragma unroll
            for (int i = 0; i < 8; i++)
#pragma unroll
                for (int j = 0; j < 8; j++)
                    acc[i][j] = fmaf(av[i], bv[j], acc[i][j]);
        }
        __syncthreads();
    }
    const bool hb = (bias != nullptr);
#pragma unroll
    for (int i = 0; i < 8; i++) {
        int gm = m0 + tm + i;
        if (gm >= M) continue;
        float* cp = C + (size_t)gm * ldc + n0 + tn;
#pragma unroll
        for (int j = 0; j < 8; j++) {
            float v = acc[i][j];
            if (hb) v += bias[n0 + tn + j];
            if (ACT == 1) v = gelu_exact(v);
            if (ACCUM) v += cp[j];
            cp[j] = v;
        }
    }
}

// ---------------- comb[r] = tri_W[r] @ node_W[r]  (256x256x256, tiny) --------
__global__ void combw_kernel(const float* __restrict__ nodeW,
                             const float* __restrict__ triW,
                             float* __restrict__ comb)
{
    __shared__ float Ts[16][16];
    __shared__ float Ns[16][17];
    int r  = blockIdx.z;
    int ii = blockIdx.y * 16 + threadIdx.y;
    int kk = blockIdx.x * 16 + threadIdx.x;
    const float* tw = triW  + (size_t)r * DD * DD;
    const float* nw = nodeW + (size_t)r * DD * DD;
    float s = 0.f;
    for (int j0 = 0; j0 < DD; j0 += 16) {
        Ts[threadIdx.y][threadIdx.x] = tw[(size_t)ii * DD + j0 + threadIdx.x];
        Ns[threadIdx.y][threadIdx.x] = nw[(size_t)(j0 + threadIdx.y) * DD + kk];
        __syncthreads();
#pragma unroll
        for (int j = 0; j < 16; j++) s = fmaf(Ts[threadIdx.y][j], Ns[j][threadIdx.x], s);
        __syncthreads();
    }
    comb[((size_t)r * DD + ii) * DD + kk] = s;
}

// ---------------- misc elementwise kernels -----------------------------------
__global__ void zero_kernel(float* p, size_t n) {
    size_t i = (size_t)blockIdx.x * blockDim.x + threadIdx.x;
    if (i < n) p[i] = 0.f;
}

// scatter tri_msg rows into node_msg at the triangle's 3 node indices (+counts)
__global__ void scatter_kernel(const float* __restrict__ tmsg,
                               const int* __restrict__ tri,
                               float* __restrict__ nmsg, float* __restrict__ cnt)
{
    int gw   = (int)(((size_t)blockIdx.x * blockDim.x + threadIdx.x) >> 5);
    int lane = threadIdx.x & 31;
    if (gw >= TT) return;
    int t0 = tri[gw], t1 = tri[TT + gw], t2 = tri[2 * TT + gw];
    const float* row = tmsg + (size_t)gw * DD;
    float v[8];
#pragma unroll
    for (int e = 0; e < 8; e++) v[e] = row[lane + 32 * e];
    float* p0 = nmsg + (size_t)t0 * DD;
    float* p1 = nmsg + (size_t)t1 * DD;
    float* p2 = nmsg + (size_t)t2 * DD;
#pragma unroll
    for (int e = 0; e < 8; e++) {
        int d = lane + 32 * e;
        atomicAdd(p0 + d, v[e]);
        atomicAdd(p1 + d, v[e]);
        atomicAdd(p2 + d, v[e]);
    }
    if (lane == 0) {
        atomicAdd(cnt + t0, 1.f);
        atomicAdd(cnt + t1, 1.f);
        atomicAdd(cnt + t2, 1.f);
    }
}

__global__ void u_kernel(const float* __restrict__ nmsg,
                         const float* __restrict__ cnt, float* __restrict__ u)
{
    size_t i = (size_t)blockIdx.x * blockDim.x + threadIdx.x;
    if (i >= ND) return;
    int n = (int)(i >> 8);
    float c = fmaxf(cnt[n], 1.f);
    float v = nmsg[i] / c;
    u[i] = v > 0.f ? v : expm1f(v);    // ELU(alpha=1)
}

__global__ void h_kernel(const float* __restrict__ u, const float* __restrict__ glog,
                         const float* __restrict__ xres, float* __restrict__ dst)
{
    size_t i = (size_t)blockIdx.x * blockDim.x + threadIdx.x;
    if (i >= ND) return;
    float a = 1.f / (1.f + expf(-glog[i]));
    dst[i] = tanhf(u[i]) * a + xres[i] * (1.f - a);
}

// ---------------- attention over relation axis (R=4): warp per (node, head) --
__global__ void attn_kernel(const float* __restrict__ qkv, float* __restrict__ oat)
{
    size_t gt = (size_t)blockIdx.x * blockDim.x + threadIdx.x;
    int gw   = (int)(gt >> 5);
    int lane = threadIdx.x & 31;
    if (gw >= NN * HH) return;
    int n = gw >> 1, h = gw & 1;

    float q[4][4], k[4][4], v[4][4];
#pragma unroll
    for (int r = 0; r < RR; r++) {
        const float* base = qkv + ((size_t)r * NN + n) * (3 * DD) + h * 128 + lane;
#pragma unroll
        for (int e = 0; e < 4; e++) {
            q[r][e] = base[32 * e];
            k[r][e] = base[256 + 32 * e];
            v[r][e] = base[512 + 32 * e];
        }
    }
    float s[4][4];
#pragma unroll
    for (int a = 0; a < 4; a++)
#pragma unroll
        for (int b = 0; b < 4; b++) {
            float p = 0.f;
#pragma unroll
            for (int e = 0; e < 4; e++) p = fmaf(q[a][e], k[b][e], p);
            s[a][b] = warp_sum(p) * 0.08838834764831845f;  // 1/sqrt(128)
        }
    float o[4][4];
#pragma unroll
    for (int a = 0; a < 4; a++)
#pragma unroll
        for (int e = 0; e < 4; e++) o[a][e] = 0.f;
#pragma unroll
    for (int a = 0; a < 4; a++) {
        float m = fmaxf(fmaxf(s[a][0], s[a][1]), fmaxf(s[a][2], s[a][3]));
        float p[4]; float sum = 0.f;
#pragma unroll
        for (int b = 0; b < 4; b++) { p[b] = expf(s[a][b] - m); sum += p[b]; }
        float inv = 1.f / sum;
#pragma unroll
        for (int b = 0; b < 4; b++) {
            float wgt = p[b] * inv;
#pragma unroll
            for (int e = 0; e < 4; e++) o[a][e] = fmaf(wgt, v[b][e], o[a][e]);
        }
    }
#pragma unroll
    for (int a = 0; a < 4; a++) {
        float* dst = oat + ((size_t)a * NN + n) * DD + h * 128 + lane;
#pragma unroll
        for (int e = 0; e < 4; e++) dst[32 * e] = o[a][e];
    }
}

// ---------------- LayerNorm(A+B) per row, warp per row -----------------------
__global__ void ln_add_kernel(const float* __restrict__ A, const float* __restrict__ Bv,
                              const float* __restrict__ g, const float* __restrict__ bb,
                              float* __restrict__ out, size_t rows)
{
    size_t gt = (size_t)blockIdx.x * blockDim.x + threadIdx.x;
    size_t w  = gt >> 5;
    int lane  = threadIdx.x & 31;
    if (w >= rows) return;
    const float* pa = A + w * DD;
    const float* pb = Bv + w * DD;
    float y[8]; float s = 0.f;
#pragma unroll
    for (int e = 0; e < 8; e++) { int d = lane + 32 * e; y[e] = pa[d] + pb[d]; s += y[e]; }
    s = warp_sum(s);
    float mean = s * (1.f / DD);
    float vs = 0.f;
#pragma unroll
    for (int e = 0; e < 8; e++) { float dv = y[e] - mean; vs += dv * dv; }
    vs = warp_sum(vs);
    float inv = rsqrtf(vs * (1.f / DD) + 1e-5f);
    float* po = out + w * DD;
#pragma unroll
    for (int e = 0; e < 8; e++) {
        int d = lane + 32 * e;
        po[d] = (y[e] - mean) * inv * g[d] + bb[d];
    }
}

// ---------------- final: mean over R of LN(x1+ff2), warp per node ------------
__global__ void final_kernel(const float* __restrict__ x1, const float* __restrict__ ff2,
                             const float* __restrict__ g, const float* __restrict__ bb,
                             float* __restrict__ out)
{
    size_t gt = (size_t)blockIdx.x * blockDim.x + threadIdx.x;
    size_t n  = gt >> 5;
    int lane  = threadIdx.x & 31;
    if (n >= NN) return;
    float acc[8];
#pragma unroll
    for (int e = 0; e < 8; e++) acc[e] = 0.f;
    for (int r = 0; r < RR; r++) {
        size_t off = ((size_t)r * NN + n) * DD;
        float y[8]; float s = 0.f;
#pragma unroll
        for (int e = 0; e < 8; e++) {
            int d = lane + 32 * e;
            y[e] = x1[off + d] + ff2[off + d];
            s += y[e];
        }
        s = warp_sum(s);
        float mean = s * (1.f / DD);
        float vs = 0.f;
#pragma unroll
        for (int e = 0; e < 8; e++) { float dv = y[e] - mean; vs += dv * dv; }
        vs = warp_sum(vs);
        float inv = rsqrtf(vs * (1.f / DD) + 1e-5f);
#pragma unroll
        for (int e = 0; e < 8; e++) {
            int d = lane + 32 * e;
            acc[e] += (y[e] - mean) * inv * g[d] + bb[d];
        }
    }
#pragma unroll
    for (int e = 0; e < 8; e++) out[n * DD + lane + 32 * e] = acc[e] * 0.25f;
}

// ---------------- launch ------------------------------------------------------
extern "C" void kernel_launch(void* const* d_in, const int* in_sizes, int n_in,
                              void* d_out, int out_size)
{
    const float* x     = (const float*)d_in[0];
    const int*   tris  = (const int*)  d_in[1];
    // d_in[2] = edge_index (unused)
    const float* nodeW = (const float*)d_in[3];
    const float* triW  = (const float*)d_in[4];
    const float* resW  = (const float*)d_in[5];
    const float* gateW = (const float*)d_in[6];
    const float* gateB = (const float*)d_in[7];
    const float* inW   = (const float*)d_in[8];
    const float* inB   = (const float*)d_in[9];
    const float* outW  = (const float*)d_in[10];
    const float* outB  = (const float*)d_in[11];
    const float* ln1g  = (const float*)d_in[12];
    const float* ln1b  = (const float*)d_in[13];
    const float* lin1W = (const float*)d_in[14];
    const float* lin1b = (const float*)d_in[15];
    const float* lin2W = (const float*)d_in[16];
    const float* lin2b = (const float*)d_in[17];
    const float* ln2g  = (const float*)d_in[18];
    const float* ln2b  = (const float*)d_in[19];
    float* out = (float*)d_out;

    float* arena;
    float* comb;
    cudaGetSymbolAddress((void**)&arena, g_arena);
    cudaGetSymbolAddress((void**)&comb,  g_comb);

    // ---- aliased buffer map ----
    float* src   = arena;               // [0, RND)
    float* big   = arena + RND;         // [RND, 4*RND)
    float* t2    = arena + 4 * RND;     // [4*RND, 5*RND)
    // phase A scratch inside `big` (qkv not live yet):
    float* xres  = big;                 // ND
    float* u     = big + ND;            // ND
    float* glog  = big + 2 * ND;        // ND
    float* nmsg  = big + 3 * ND;        // ND
    float* tmsg  = big + 4 * ND;        // TT*DD (38.4M) < ND+… fits
    float* cnt   = big + 6 * ND;        // NN floats
    // phase B:
    float* qkv   = big;                 // 3*RND
    float* oattn = t2;                  // RND
    float* oproj = big;                 // RND (qkv dead after attn)
    float* x1    = src;                 // in-place LN over src+oproj
    float* ff1   = big;                 // 2*RND (oproj dead after ln_add)
    float* ff2   = t2;                  // RND (oattn dead)

    dim3 blk(256);

    // fused relation weights: comb[r] = tri_W[r] @ node_W[r]
    combw_kernel<<<dim3(16, 16, RR), dim3(16, 16)>>>(nodeW, triW, comb);

    // x_res = x @ res_W^T
    sgemm_kernel<0, 0, 0><<<dim3(782, 2), blk>>>(x, resW, xres, nullptr, nullptr, 0,
                                                 NN, DD, DD, DD, DD, DD);

    for (int r = 0; r < RR; r++) {
        const int* trir = tris + (size_t)r * 3 * TT;
        zero_kernel<<<(unsigned)(ND / 256), blk>>>(nmsg, ND);
        zero_kernel<<<(NN + 255) / 256, blk>>>(cnt, (size_t)NN);
        // tri_msg = mean(x[tri]) @ comb[r]^T  (gather fused into A loads)
        sgemm_kernel<1, 0, 0><<<dim3(1172, 2), blk>>>(x, comb + (size_t)r * DD * DD,
                                                      tmsg, nullptr, trir, TT,
                                                      TT, DD, DD, DD, DD, DD);
        scatter_kernel<<<18750, blk>>>(tmsg, trir, nmsg, cnt);
        u_kernel<<<(unsigned)(ND / 256), blk>>>(nmsg, cnt, u);
        // gate logits: x @ W1^T + b, then += u @ W2^T   (gate_W is [D, 2D])
        sgemm_kernel<0, 0, 0><<<dim3(782, 2), blk>>>(x, gateW, glog, gateB, nullptr, 0,
                                                     NN, DD, DD, DD, 2 * DD, DD);
        sgemm_kernel<0, 0, 1><<<dim3(782, 2), blk>>>(u, gateW + DD, glog, nullptr, nullptr, 0,
                                                     NN, DD, DD, DD, 2 * DD, DD);
        h_kernel<<<(unsigned)(ND / 256), blk>>>(u, glog, xres, src + (size_t)r * ND);
    }

    // qkv = src @ in_W^T + in_b     [400000 x 768]
    sgemm_kernel<0, 0, 0><<<dim3(3125, 6), blk>>>(src, inW, qkv, inB, nullptr, 0,
                                                  RR * NN, 3 * DD, DD, DD, DD, 3 * DD);
    attn_kernel<<<25000, blk>>>(qkv, oattn);
    // o = o_attn @ out_W^T + out_b   (writes over qkv region — qkv is dead)
    sgemm_kernel<0, 0, 0><<<dim3(3125, 2), blk>>>(oattn, outW, oproj, outB, nullptr, 0,
                                                  RR * NN, DD, DD, DD, DD, DD);
    // x1 = LN(src + o)  (in-place over src)
    ln_add_kernel<<<50000, blk>>>(src, oproj, ln1g, ln1b, x1, (size_t)RR * NN);
    // ff1 = gelu(x1 @ lin1_W^T + lin1_b)   [400000 x 512]
    sgemm_kernel<0, 1, 0><<<dim3(3125, 4), blk>>>(x1, lin1W, ff1, lin1b, nullptr, 0,
                                                  RR * NN, 2 * DD, DD, DD, DD, 2 * DD);
    // ff2 = ff1 @ lin2_W^T + lin2_b
    sgemm_kernel<0, 0, 0><<<dim3(3125, 2), blk>>>(ff1, lin2W, ff2, lin2b, nullptr, 0,
                                                  RR * NN, DD, 2 * DD, 2 * DD, 2 * DD, DD);
    // out = mean_r LN(x1 + ff2)
    final_kernel<<<12500, blk>>>(x1, ff2, ln2g, ln2b, out);
}

// round 3
// speedup vs baseline: 1.8518x; 1.8518x over previous
#include <cuda_runtime.h>
#include <math.h>
#include <stddef.h>
#include <stdint.h>

#define NN 100000
#define DD 256
#define RR 4
#define TT 150000
#define HH 2

constexpr size_t ND  = (size_t)NN * DD;         // 25.6M floats
constexpr size_t RND = (size_t)RR * NN * DD;    // 102.4M floats

// ---- single scratch arena (2.05 GB) with lifetime-based aliasing ----
__device__ float g_arena[5 * RND];
__device__ float g_comb[(size_t)RR * DD * DD];

// ---------------- helpers ----------------------------------------------------
__device__ __forceinline__ float warp_sum(float v) {
#pragma unroll
    for (int o = 16; o; o >>= 1) v += __shfl_xor_sync(0xffffffffu, v, o);
    return v;
}
__device__ __forceinline__ float gelu_exact(float x) {
    return 0.5f * x * (1.0f + erff(x * 0.7071067811865475f));
}
__device__ __forceinline__ uint32_t f2tf32(float x) {
    uint32_t r;
    asm("cvt.rna.tf32.f32 %0, %1;" : "=r"(r) : "f"(x));
    return r;
}
__device__ __forceinline__ void mma_tf32(float& c0, float& c1, float& c2, float& c3,
                                         uint32_t a0, uint32_t a1, uint32_t a2, uint32_t a3,
                                         uint32_t b0, uint32_t b1) {
    asm volatile(
        "mma.sync.aligned.m16n8k8.row.col.f32.tf32.tf32.f32 "
        "{%0,%1,%2,%3}, {%4,%5,%6,%7}, {%8,%9}, {%0,%1,%2,%3};"
        : "+f"(c0), "+f"(c1), "+f"(c2), "+f"(c3)
        : "r"(a0), "r"(a1), "r"(a2), "r"(a3), "r"(b0), "r"(b1));
}

// ---------------- TF32 tensor-core GEMM: C[M,Nc] = A[M,K] @ B[Nc,K]^T --------
// TRIA: A rows are gathered means of 3 x-rows per triangle index.
// ACT==1: GELU epilogue. bias optional.
#define BM 128
#define BN 128
#define BK 16
#define PAD 4

template <int TRIA, int ACT>
__global__ __launch_bounds__(256, 2)
void gemm_tc(const float* __restrict__ A, const float* __restrict__ B,
             float* __restrict__ C, const float* __restrict__ bias,
             const int* __restrict__ tri, int triN,
             int M, int K, int lda, int ldb, int ldc)
{
    __shared__ uint32_t As[BK][BM + PAD];
    __shared__ uint32_t Bs[BK][BN + PAD];
    const int t   = threadIdx.x;
    const int m0  = blockIdx.x * BM;
    const int n0  = blockIdx.y * BN;
    const int w   = t >> 5, lane = t & 31;
    const int wm  = w >> 2;          // 2 warps along M (64 rows each)
    const int wn  = w & 3;           // 4 warps along N (32 cols each)
    const int g   = lane >> 2;       // group id 0..7
    const int c4  = lane & 3;        // thread-in-group 0..3

    float acc[4][4][4];              // [mfrag][nfrag][c0..c3]
#pragma unroll
    for (int i = 0; i < 4; i++)
#pragma unroll
        for (int j = 0; j < 4; j++)
#pragma unroll
            for (int e = 0; e < 4; e++) acc[i][j][e] = 0.f;

    for (int kk = 0; kk < K; kk += BK) {
        // --- load A tile (128 rows x 16 k), convert to tf32, store [k][m] ---
#pragma unroll
        for (int qd = 0; qd < 2; qd++) {
            int idx = t + qd * 256;
            int row = idx >> 2;
            int kq  = (idx & 3) << 2;
            float4 va = make_float4(0.f, 0.f, 0.f, 0.f);
            int gr = m0 + row;
            if (gr < M) {
                if (TRIA) {
                    int i0 = tri[gr], i1 = tri[triN + gr], i2 = tri[2 * triN + gr];
                    float4 a0 = *(const float4*)(A + (size_t)i0 * lda + kk + kq);
                    float4 a1 = *(const float4*)(A + (size_t)i1 * lda + kk + kq);
                    float4 a2 = *(const float4*)(A + (size_t)i2 * lda + kk + kq);
                    const float third = 1.f / 3.f;
                    va.x = (a0.x + a1.x + a2.x) * third;
                    va.y = (a0.y + a1.y + a2.y) * third;
                    va.z = (a0.z + a1.z + a2.z) * third;
                    va.w = (a0.w + a1.w + a2.w) * third;
                } else {
                    va = *(const float4*)(A + (size_t)gr * lda + kk + kq);
                }
            }
            As[kq + 0][row] = f2tf32(va.x); As[kq + 1][row] = f2tf32(va.y);
            As[kq + 2][row] = f2tf32(va.z); As[kq + 3][row] = f2tf32(va.w);
        }
        // --- load B tile (128 n-rows x 16 k), store [k][n] ---
#pragma unroll
        for (int qd = 0; qd < 2; qd++) {
            int idx = t + qd * 256;
            int row = idx >> 2;
            int kq  = (idx & 3) << 2;
            float4 vb = *(const float4*)(B + (size_t)(n0 + row) * ldb + kk + kq);
            Bs[kq + 0][row] = f2tf32(vb.x); Bs[kq + 1][row] = f2tf32(vb.y);
            Bs[kq + 2][row] = f2tf32(vb.z); Bs[kq + 3][row] = f2tf32(vb.w);
        }
        __syncthreads();
#pragma unroll
        for (int kb = 0; kb < BK; kb += 8) {
            uint32_t af[4][4];
#pragma unroll
            for (int mf = 0; mf < 4; mf++) {
                int mr = wm * 64 + mf * 16 + g;
                af[mf][0] = As[kb + c4][mr];
                af[mf][1] = As[kb + c4][mr + 8];
                af[mf][2] = As[kb + c4 + 4][mr];
                af[mf][3] = As[kb + c4 + 4][mr + 8];
            }
#pragma unroll
            for (int nf = 0; nf < 4; nf++) {
                int nc = wn * 32 + nf * 8 + g;
                uint32_t b0 = Bs[kb + c4][nc];
                uint32_t b1 = Bs[kb + c4 + 4][nc];
#pragma unroll
                for (int mf = 0; mf < 4; mf++)
                    mma_tf32(acc[mf][nf][0], acc[mf][nf][1], acc[mf][nf][2], acc[mf][nf][3],
                             af[mf][0], af[mf][1], af[mf][2], af[mf][3], b0, b1);
            }
        }
        __syncthreads();
    }

    // --- epilogue ---
    const bool hb = (bias != nullptr);
#pragma unroll
    for (int mf = 0; mf < 4; mf++) {
#pragma unroll
        for (int half = 0; half < 2; half++) {
            int gm = m0 + wm * 64 + mf * 16 + g + half * 8;
            if (gm >= M) continue;
            float* cp = C + (size_t)gm * ldc + n0 + wn * 32;
#pragma unroll
            for (int nf = 0; nf < 4; nf++) {
                int col = nf * 8 + c4 * 2;
                float v0 = acc[mf][nf][half * 2 + 0];
                float v1 = acc[mf][nf][half * 2 + 1];
                if (hb) {
                    v0 += bias[n0 + wn * 32 + col];
                    v1 += bias[n0 + wn * 32 + col + 1];
                }
                if (ACT == 1) { v0 = gelu_exact(v0); v1 = gelu_exact(v1); }
                *(float2*)(cp + col) = make_float2(v0, v1);
            }
        }
    }
}

// ---------------- comb[r] = tri_W[r] @ node_W[r]  (tiny, fp32 SIMT) ----------
__global__ void combw_kernel(const float* __restrict__ nodeW,
                             const float* __restrict__ triW,
                             float* __restrict__ comb)
{
    __shared__ float Ts[16][16];
    __shared__ float Ns[16][17];
    int r  = blockIdx.z;
    int ii = blockIdx.y * 16 + threadIdx.y;
    int kk = blockIdx.x * 16 + threadIdx.x;
    const float* tw = triW  + (size_t)r * DD * DD;
    const float* nw = nodeW + (size_t)r * DD * DD;
    float s = 0.f;
    for (int j0 = 0; j0 < DD; j0 += 16) {
        Ts[threadIdx.y][threadIdx.x] = tw[(size_t)ii * DD + j0 + threadIdx.x];
        Ns[threadIdx.y][threadIdx.x] = nw[(size_t)(j0 + threadIdx.y) * DD + kk];
        __syncthreads();
#pragma unroll
        for (int j = 0; j < 16; j++) s = fmaf(Ts[threadIdx.y][j], Ns[j][threadIdx.x], s);
        __syncthreads();
    }
    comb[((size_t)r * DD + ii) * DD + kk] = s;
}

// ---------------- misc elementwise kernels -----------------------------------
__global__ void zero_kernel(float* p, size_t n) {
    size_t i = (size_t)blockIdx.x * blockDim.x + threadIdx.x;
    if (i < n) p[i] = 0.f;
}

__global__ void scatter_kernel(const float* __restrict__ tmsg,
                               const int* __restrict__ tri,
                               float* __restrict__ nmsg, float* __restrict__ cnt)
{
    int gw   = (int)(((size_t)blockIdx.x * blockDim.x + threadIdx.x) >> 5);
    int lane = threadIdx.x & 31;
    if (gw >= TT) return;
    int t0 = tri[gw], t1 = tri[TT + gw], t2 = tri[2 * TT + gw];
    const float* row = tmsg + (size_t)gw * DD;
    float v[8];
#pragma unroll
    for (int e = 0; e < 8; e++) v[e] = row[lane + 32 * e];
    float* p0 = nmsg + (size_t)t0 * DD;
    float* p1 = nmsg + (size_t)t1 * DD;
    float* p2 = nmsg + (size_t)t2 * DD;
#pragma unroll
    for (int e = 0; e < 8; e++) {
        int d = lane + 32 * e;
        atomicAdd(p0 + d, v[e]);
        atomicAdd(p1 + d, v[e]);
        atomicAdd(p2 + d, v[e]);
    }
    if (lane == 0) {
        atomicAdd(cnt + t0, 1.f);
        atomicAdd(cnt + t1, 1.f);
        atomicAdd(cnt + t2, 1.f);
    }
}

__global__ void u_kernel(const float* __restrict__ nmsg,
                         const float* __restrict__ cnt, float* __restrict__ u)
{
    size_t i = (size_t)blockIdx.x * blockDim.x + threadIdx.x;
    if (i >= ND) return;
    int n = (int)(i >> 8);
    float c = fmaxf(cnt[n], 1.f);
    float v = nmsg[i] / c;
    u[i] = v > 0.f ? v : expm1f(v);    // ELU(alpha=1)
}

__global__ void h_kernel(const float* __restrict__ u,
                         const float* __restrict__ glog1, const float* __restrict__ glog2,
                         const float* __restrict__ xres, float* __restrict__ dst)
{
    size_t i = (size_t)blockIdx.x * blockDim.x + threadIdx.x;
    if (i >= ND) return;
    float a = 1.f / (1.f + expf(-(glog1[i] + glog2[i])));
    dst[i] = tanhf(u[i]) * a + xres[i] * (1.f - a);
}

// ---------------- attention over relation axis (R=4): warp per (node, head) --
__global__ void attn_kernel(const float* __restrict__ qkv, float* __restrict__ oat)
{
    size_t gt = (size_t)blockIdx.x * blockDim.x + threadIdx.x;
    int gw   = (int)(gt >> 5);
    int lane = threadIdx.x & 31;
    if (gw >= NN * HH) return;
    int n = gw >> 1, h = gw & 1;

    float q[4][4], k[4][4], v[4][4];
#pragma unroll
    for (int r = 0; r < RR; r++) {
        const float* base = qkv + ((size_t)r * NN + n) * (3 * DD) + h * 128 + lane;
#pragma unroll
        for (int e = 0; e < 4; e++) {
            q[r][e] = base[32 * e];
            k[r][e] = base[256 + 32 * e];
            v[r][e] = base[512 + 32 * e];
        }
    }
    float s[4][4];
#pragma unroll
    for (int a = 0; a < 4; a++)
#pragma unroll
        for (int b = 0; b < 4; b++) {
            float p = 0.f;
#pragma unroll
            for (int e = 0; e < 4; e++) p = fmaf(q[a][e], k[b][e], p);
            s[a][b] = warp_sum(p) * 0.08838834764831845f;  // 1/sqrt(128)
        }
    float o[4][4];
#pragma unroll
    for (int a = 0; a < 4; a++)
#pragma unroll
        for (int e = 0; e < 4; e++) o[a][e] = 0.f;
#pragma unroll
    for (int a = 0; a < 4; a++) {
        float m = fmaxf(fmaxf(s[a][0], s[a][1]), fmaxf(s[a][2], s[a][3]));
        float p[4]; float sum = 0.f;
#pragma unroll
        for (int b = 0; b < 4; b++) { p[b] = expf(s[a][b] - m); sum += p[b]; }
        float inv = 1.f / sum;
#pragma unroll
        for (int b = 0; b < 4; b++) {
            float wgt = p[b] * inv;
#pragma unroll
            for (int e = 0; e < 4; e++) o[a][e] = fmaf(wgt, v[b][e], o[a][e]);
        }
    }
#pragma unroll
    for (int a = 0; a < 4; a++) {
        float* dst = oat + ((size_t)a * NN + n) * DD + h * 128 + lane;
#pragma unroll
        for (int e = 0; e < 4; e++) dst[32 * e] = o[a][e];
    }
}

// ---------------- LayerNorm(A+B) per row, warp per row -----------------------
__global__ void ln_add_kernel(const float* __restrict__ A, const float* __restrict__ Bv,
                              const float* __restrict__ g, const float* __restrict__ bb,
                              float* __restrict__ out, size_t rows)
{
    size_t gt = (size_t)blockIdx.x * blockDim.x + threadIdx.x;
    size_t w  = gt >> 5;
    int lane  = threadIdx.x & 31;
    if (w >= rows) return;
    const float* pa = A + w * DD;
    const float* pb = Bv + w * DD;
    float y[8]; float s = 0.f;
#pragma unroll
    for (int e = 0; e < 8; e++) { int d = lane + 32 * e; y[e] = pa[d] + pb[d]; s += y[e]; }
    s = warp_sum(s);
    float mean = s * (1.f / DD);
    float vs = 0.f;
#pragma unroll
    for (int e = 0; e < 8; e++) { float dv = y[e] - mean; vs += dv * dv; }
    vs = warp_sum(vs);
    float inv = rsqrtf(vs * (1.f / DD) + 1e-5f);
    float* po = out + w * DD;
#pragma unroll
    for (int e = 0; e < 8; e++) {
        int d = lane + 32 * e;
        po[d] = (y[e] - mean) * inv * g[d] + bb[d];
    }
}

// ---------------- final: mean over R of LN(x1+ff2), warp per node ------------
__global__ void final_kernel(const float* __restrict__ x1, const float* __restrict__ ff2,
                             const float* __restrict__ g, const float* __restrict__ bb,
                             float* __restrict__ out)
{
    size_t gt = (size_t)blockIdx.x * blockDim.x + threadIdx.x;
    size_t n  = gt >> 5;
    int lane  = threadIdx.x & 31;
    if (n >= NN) return;
    float acc[8];
#pragma unroll
    for (int e = 0; e < 8; e++) acc[e] = 0.f;
    for (int r = 0; r < RR; r++) {
        size_t off = ((size_t)r * NN + n) * DD;
        float y[8]; float s = 0.f;
#pragma unroll
        for (int e = 0; e < 8; e++) {
            int d = lane + 32 * e;
            y[e] = x1[off + d] + ff2[off + d];
            s += y[e];
        }
        s = warp_sum(s);
        float mean = s * (1.f / DD);
        float vs = 0.f;
#pragma unroll
        for (int e = 0; e < 8; e++) { float dv = y[e] - mean; vs += dv * dv; }
        vs = warp_sum(vs);
        float inv = rsqrtf(vs * (1.f / DD) + 1e-5f);
#pragma unroll
        for (int e = 0; e < 8; e++) {
            int d = lane + 32 * e;
            acc[e] += (y[e] - mean) * inv * g[d] + bb[d];
        }
    }
#pragma unroll
    for (int e = 0; e < 8; e++) out[n * DD + lane + 32 * e] = acc[e] * 0.25f;
}

// ---------------- launch ------------------------------------------------------
extern "C" void kernel_launch(void* const* d_in, const int* in_sizes, int n_in,
                              void* d_out, int out_size)
{
    const float* x     = (const float*)d_in[0];
    const int*   tris  = (const int*)  d_in[1];
    // d_in[2] = edge_index (unused)
    const float* nodeW = (const float*)d_in[3];
    const float* triW  = (const float*)d_in[4];
    const float* resW  = (const float*)d_in[5];
    const float* gateW = (const float*)d_in[6];
    const float* gateB = (const float*)d_in[7];
    const float* inW   = (const float*)d_in[8];
    const float* inB   = (const float*)d_in[9];
    const float* outW  = (const float*)d_in[10];
    const float* outB  = (const float*)d_in[11];
    const float* ln1g  = (const float*)d_in[12];
    const float* ln1b  = (const float*)d_in[13];
    const float* lin1W = (const float*)d_in[14];
    const float* lin1b = (const float*)d_in[15];
    const float* lin2W = (const float*)d_in[16];
    const float* lin2b = (const float*)d_in[17];
    const float* ln2g  = (const float*)d_in[18];
    const float* ln2b  = (const float*)d_in[19];
    float* out = (float*)d_out;

    float* arena;
    float* comb;
    cudaGetSymbolAddress((void**)&arena, g_arena);
    cudaGetSymbolAddress((void**)&comb,  g_comb);

    // ---- aliased buffer map ----
    float* src   = arena;               // [0, RND)
    float* big   = arena + RND;         // [RND, 4*RND) = 12*ND
    float* t2    = arena + 4 * RND;     // [4*RND, 5*RND)
    // phase A scratch inside `big` (qkv not live yet):
    float* xres  = big;                 // ND
    float* u     = big + ND;            // ND
    float* glog1 = big + 2 * ND;        // ND (relation-invariant gate part)
    float* glog2 = big + 3 * ND;        // ND
    float* nmsg  = big + 4 * ND;        // ND
    float* tmsg  = big + 5 * ND;        // 1.5*ND (TT*DD)
    float* cnt   = big + 7 * ND;        // NN floats
    // phase B:
    float* qkv   = big;                 // 3*RND
    float* oattn = t2;                  // RND
    float* oproj = big;                 // RND (qkv dead after attn)
    float* x1    = src;                 // in-place LN over src+oproj
    float* ff1   = big;                 // 2*RND (oproj dead after ln_add)
    float* ff2   = t2;                  // RND (oattn dead)

    dim3 blk(256);

    // fused relation weights: comb[r] = tri_W[r] @ node_W[r]
    combw_kernel<<<dim3(16, 16, RR), dim3(16, 16)>>>(nodeW, triW, comb);

    // x_res = x @ res_W^T
    gemm_tc<0, 0><<<dim3(782, 2), blk>>>(x, resW, xres, nullptr, nullptr, 0,
                                         NN, DD, DD, DD, DD);
    // relation-invariant gate half: glog1 = x @ W1^T + b
    gemm_tc<0, 0><<<dim3(782, 2), blk>>>(x, gateW, glog1, gateB, nullptr, 0,
                                         NN, DD, DD, 2 * DD, DD);

    for (int r = 0; r < RR; r++) {
        const int* trir = tris + (size_t)r * 3 * TT;
        zero_kernel<<<(unsigned)(ND / 256), blk>>>(nmsg, ND);
        zero_kernel<<<(NN + 255) / 256, blk>>>(cnt, (size_t)NN);
        // tri_msg = mean(x[tri]) @ comb[r]^T  (gather fused into A loads)
        gemm_tc<1, 0><<<dim3(1172, 2), blk>>>(x, comb + (size_t)r * DD * DD,
                                              tmsg, nullptr, trir, TT,
                                              TT, DD, DD, DD, DD);
        scatter_kernel<<<18750, blk>>>(tmsg, trir, nmsg, cnt);
        u_kernel<<<(unsigned)(ND / 256), blk>>>(nmsg, cnt, u);
        // relation-dependent gate half: glog2 = u @ W2^T
        gemm_tc<0, 0><<<dim3(782, 2), blk>>>(u, gateW + DD, glog2, nullptr, nullptr, 0,
                                             NN, DD, DD, 2 * DD, DD);
        h_kernel<<<(unsigned)(ND / 256), blk>>>(u, glog1, glog2, xres, src + (size_t)r * ND);
    }

    // qkv = src @ in_W^T + in_b     [400000 x 768]
    gemm_tc<0, 0><<<dim3(3125, 6), blk>>>(src, inW, qkv, inB, nullptr, 0,
                                          RR * NN, DD, DD, DD, 3 * DD);
    attn_kernel<<<25000, blk>>>(qkv, oattn);
    // o = o_attn @ out_W^T + out_b
    gemm_tc<0, 0><<<dim3(3125, 2), blk>>>(oattn, outW, oproj, outB, nullptr, 0,
                                          RR * NN, DD, DD, DD, DD);
    // x1 = LN(src + o)  (in-place over src)
    ln_add_kernel<<<50000, blk>>>(src, oproj, ln1g, ln1b, x1, (size_t)RR * NN);
    // ff1 = gelu(x1 @ lin1_W^T + lin1_b)   [400000 x 512]
    gemm_tc<0, 1><<<dim3(3125, 4), blk>>>(x1, lin1W, ff1, lin1b, nullptr, 0,
                                          RR * NN, DD, DD, DD, 2 * DD);
    // ff2 = ff1 @ lin2_W^T + lin2_b
    gemm_tc<0, 0><<<dim3(3125, 2), blk>>>(ff1, lin2W, ff2, lin2b, nullptr, 0,
                                          RR * NN, 2 * DD, 2 * DD, 2 * DD, DD);
    // out = mean_r LN(x1 + ff2)
    final_kernel<<<12500, blk>>>(x1, ff2, ln2g, ln2b, out);
}

// round 4
// speedup vs baseline: 2.0302x; 1.0964x over previous
#include <cuda_runtime.h>
#include <math.h>
#include <stddef.h>
#include <stdint.h>

#define NN 100000
#define DD 256
#define RR 4
#define TT 150000
#define HH 2

constexpr size_t ND  = (size_t)NN * DD;         // 25.6M floats
constexpr size_t RND = (size_t)RR * NN * DD;    // 102.4M floats

// ---- single scratch arena (2.05 GB) with lifetime-based aliasing ----
__device__ float g_arena[5 * RND];
__device__ float g_comb[(size_t)RR * DD * DD];

// ---------------- helpers ----------------------------------------------------
__device__ __forceinline__ float warp_sum(float v) {
#pragma unroll
    for (int o = 16; o; o >>= 1) v += __shfl_xor_sync(0xffffffffu, v, o);
    return v;
}
__device__ __forceinline__ float gelu_exact(float x) {
    return 0.5f * x * (1.0f + erff(x * 0.7071067811865475f));
}
__device__ __forceinline__ uint32_t f2tf32(float x) {
    uint32_t r;
    asm("cvt.rna.tf32.f32 %0, %1;" : "=r"(r) : "f"(x));
    return r;
}
__device__ __forceinline__ void mma_tf32(float& c0, float& c1, float& c2, float& c3,
                                         uint32_t a0, uint32_t a1, uint32_t a2, uint32_t a3,
                                         uint32_t b0, uint32_t b1) {
    asm volatile(
        "mma.sync.aligned.m16n8k8.row.col.f32.tf32.tf32.f32 "
        "{%0,%1,%2,%3}, {%4,%5,%6,%7}, {%8,%9}, {%0,%1,%2,%3};"
        : "+f"(c0), "+f"(c1), "+f"(c2), "+f"(c3)
        : "r"(a0), "r"(a1), "r"(a2), "r"(a3), "r"(b0), "r"(b1));
}

// ---------------- TF32 tensor-core GEMM: C[M,Nc] = A[M,K] @ B[Nc,K]^T --------
// Double-buffered smem, register prefetch, 1 sync per K-iteration.
// TRIA: A rows are gathered means of 3 x-rows per triangle index.
#define BM 128
#define BN 128
#define BK 16
#define PAD 4

template <int TRIA, int ACT>
__global__ __launch_bounds__(256, 2)
void gemm_tc(const float* __restrict__ A, const float* __restrict__ B,
             float* __restrict__ C, const float* __restrict__ bias,
             const int* __restrict__ tri, int triN,
             int M, int K, int lda, int ldb, int ldc)
{
    __shared__ uint32_t As[2][BK][BM + PAD];
    __shared__ uint32_t Bs[2][BK][BN + PAD];
    const int t   = threadIdx.x;
    const int m0  = blockIdx.x * BM;
    const int n0  = blockIdx.y * BN;
    const int w   = t >> 5, lane = t & 31;
    const int wm  = w >> 2;          // 2 warps along M (64 rows each)
    const int wn  = w & 3;           // 4 warps along N (32 cols each)
    const int g   = lane >> 2;       // group id 0..7
    const int c4  = lane & 3;        // thread-in-group 0..3

    // per-thread tile-load coordinates (2 float4 per matrix per tile)
    const int rowA0 = t >> 2,        rowA1 = (t + 256) >> 2;
    const int kqA0  = (t & 3) << 2,  kqA1  = kqA0;   // same (idx+256 keeps low bits)

    float acc[4][4][4];
#pragma unroll
    for (int i = 0; i < 4; i++)
#pragma unroll
        for (int j = 0; j < 4; j++)
#pragma unroll
            for (int e = 0; e < 4; e++) acc[i][j][e] = 0.f;

    float4 pa[2], pb[2];

    auto ldg_tile = [&](int kk) {
#pragma unroll
        for (int qd = 0; qd < 2; qd++) {
            int row = qd ? rowA1 : rowA0;
            int kq  = qd ? kqA1  : kqA0;
            float4 va = make_float4(0.f, 0.f, 0.f, 0.f);
            int gr = m0 + row;
            if (gr < M) {
                if (TRIA) {
                    int i0 = tri[gr], i1 = tri[triN + gr], i2 = tri[2 * triN + gr];
                    float4 a0 = *(const float4*)(A + (size_t)i0 * lda + kk + kq);
                    float4 a1 = *(const float4*)(A + (size_t)i1 * lda + kk + kq);
                    float4 a2 = *(const float4*)(A + (size_t)i2 * lda + kk + kq);
                    const float third = 1.f / 3.f;
                    va.x = (a0.x + a1.x + a2.x) * third;
                    va.y = (a0.y + a1.y + a2.y) * third;
                    va.z = (a0.z + a1.z + a2.z) * third;
                    va.w = (a0.w + a1.w + a2.w) * third;
                } else {
                    va = *(const float4*)(A + (size_t)gr * lda + kk + kq);
                }
            }
            pa[qd] = va;
            pb[qd] = *(const float4*)(B + (size_t)(n0 + (qd ? rowA1 : rowA0)) * ldb + kk + kq);
        }
    };
    auto sts_tile = [&](int st) {
#pragma unroll
        for (int qd = 0; qd < 2; qd++) {
            int row = qd ? rowA1 : rowA0;
            int kq  = qd ? kqA1  : kqA0;
            As[st][kq + 0][row] = f2tf32(pa[qd].x);
            As[st][kq + 1][row] = f2tf32(pa[qd].y);
            As[st][kq + 2][row] = f2tf32(pa[qd].z);
            As[st][kq + 3][row] = f2tf32(pa[qd].w);
            Bs[st][kq + 0][row] = f2tf32(pb[qd].x);
            Bs[st][kq + 1][row] = f2tf32(pb[qd].y);
            Bs[st][kq + 2][row] = f2tf32(pb[qd].z);
            Bs[st][kq + 3][row] = f2tf32(pb[qd].w);
        }
    };

    // prologue: stage 0
    ldg_tile(0);
    sts_tile(0);
    __syncthreads();

    int st = 0;
    for (int kk = 0; kk < K; kk += BK) {
        const bool more = (kk + BK) < K;
        if (more) ldg_tile(kk + BK);      // LDGs issued before compute (latency hidden)

#pragma unroll
        for (int kb = 0; kb < BK; kb += 8) {
            uint32_t af[4][4];
#pragma unroll
            for (int mf = 0; mf < 4; mf++) {
                int mr = wm * 64 + mf * 16 + g;
                af[mf][0] = As[st][kb + c4][mr];
                af[mf][1] = As[st][kb + c4][mr + 8];
                af[mf][2] = As[st][kb + c4 + 4][mr];
                af[mf][3] = As[st][kb + c4 + 4][mr + 8];
            }
#pragma unroll
            for (int nf = 0; nf < 4; nf++) {
                int nc = wn * 32 + nf * 8 + g;
                uint32_t b0 = Bs[st][kb + c4][nc];
                uint32_t b1 = Bs[st][kb + c4 + 4][nc];
#pragma unroll
                for (int mf = 0; mf < 4; mf++)
                    mma_tf32(acc[mf][nf][0], acc[mf][nf][1], acc[mf][nf][2], acc[mf][nf][3],
                             af[mf][0], af[mf][1], af[mf][2], af[mf][3], b0, b1);
            }
        }
        if (more) sts_tile(st ^ 1);       // stage st^1 fully consumed >=1 sync ago
        __syncthreads();
        st ^= 1;
    }

    // --- epilogue ---
    const bool hb = (bias != nullptr);
#pragma unroll
    for (int mf = 0; mf < 4; mf++) {
#pragma unroll
        for (int half = 0; half < 2; half++) {
            int gm = m0 + wm * 64 + mf * 16 + g + half * 8;
            if (gm >= M) continue;
            float* cp = C + (size_t)gm * ldc + n0 + wn * 32;
#pragma unroll
            for (int nf = 0; nf < 4; nf++) {
                int col = nf * 8 + c4 * 2;
                float v0 = acc[mf][nf][half * 2 + 0];
                float v1 = acc[mf][nf][half * 2 + 1];
                if (hb) {
                    v0 += bias[n0 + wn * 32 + col];
                    v1 += bias[n0 + wn * 32 + col + 1];
                }
                if (ACT == 1) { v0 = gelu_exact(v0); v1 = gelu_exact(v1); }
                *(float2*)(cp + col) = make_float2(v0, v1);
            }
        }
    }
}

// ---------------- comb[r] = tri_W[r] @ node_W[r]  (tiny, fp32 SIMT) ----------
__global__ void combw_kernel(const float* __restrict__ nodeW,
                             const float* __restrict__ triW,
                             float* __restrict__ comb)
{
    __shared__ float Ts[16][16];
    __shared__ float Ns[16][17];
    int r  = blockIdx.z;
    int ii = blockIdx.y * 16 + threadIdx.y;
    int kk = blockIdx.x * 16 + threadIdx.x;
    const float* tw = triW  + (size_t)r * DD * DD;
    const float* nw = nodeW + (size_t)r * DD * DD;
    float s = 0.f;
    for (int j0 = 0; j0 < DD; j0 += 16) {
        Ts[threadIdx.y][threadIdx.x] = tw[(size_t)ii * DD + j0 + threadIdx.x];
        Ns[threadIdx.y][threadIdx.x] = nw[(size_t)(j0 + threadIdx.y) * DD + kk];
        __syncthreads();
#pragma unroll
        for (int j = 0; j < 16; j++) s = fmaf(Ts[threadIdx.y][j], Ns[j][threadIdx.x], s);
        __syncthreads();
    }
    comb[((size_t)r * DD + ii) * DD + kk] = s;
}

// ---------------- misc elementwise kernels -----------------------------------
__global__ void scatter_kernel(const float* __restrict__ tmsg,
                               const int* __restrict__ tri,
                               float* __restrict__ nmsg, float* __restrict__ cnt)
{
    int gw   = (int)(((size_t)blockIdx.x * blockDim.x + threadIdx.x) >> 5);
    int lane = threadIdx.x & 31;
    if (gw >= TT) return;
    int t0 = tri[gw], t1 = tri[TT + gw], t2 = tri[2 * TT + gw];
    const float* row = tmsg + (size_t)gw * DD;
    float v[8];
#pragma unroll
    for (int e = 0; e < 8; e++) v[e] = row[lane + 32 * e];
    float* p0 = nmsg + (size_t)t0 * DD;
    float* p1 = nmsg + (size_t)t1 * DD;
    float* p2 = nmsg + (size_t)t2 * DD;
#pragma unroll
    for (int e = 0; e < 8; e++) {
        int d = lane + 32 * e;
        atomicAdd(p0 + d, v[e]);
        atomicAdd(p1 + d, v[e]);
        atomicAdd(p2 + d, v[e]);
    }
    if (lane == 0) {
        atomicAdd(cnt + t0, 1.f);
        atomicAdd(cnt + t1, 1.f);
        atomicAdd(cnt + t2, 1.f);
    }
}

__global__ void u_kernel(const float* __restrict__ nmsg,
                         const float* __restrict__ cnt, float* __restrict__ u)
{
    size_t i = (size_t)blockIdx.x * blockDim.x + threadIdx.x;
    if (i >= ND) return;
    int n = (int)(i >> 8);
    float c = fmaxf(cnt[n], 1.f);
    float v = nmsg[i] / c;
    u[i] = v > 0.f ? v : expm1f(v);    // ELU(alpha=1)
}

__global__ void h_kernel(const float* __restrict__ u,
                         const float* __restrict__ glog1, const float* __restrict__ glog2,
                         const float* __restrict__ xres, float* __restrict__ dst)
{
    size_t i = (size_t)blockIdx.x * blockDim.x + threadIdx.x;
    if (i >= ND) return;
    float a = 1.f / (1.f + expf(-(glog1[i] + glog2[i])));
    dst[i] = tanhf(u[i]) * a + xres[i] * (1.f - a);
}

// ---------------- attention over relation axis (R=4): warp per (node, head) --
__global__ void attn_kernel(const float* __restrict__ qkv, float* __restrict__ oat)
{
    size_t gt = (size_t)blockIdx.x * blockDim.x + threadIdx.x;
    int gw   = (int)(gt >> 5);
    int lane = threadIdx.x & 31;
    if (gw >= NN * HH) return;
    int n = gw >> 1, h = gw & 1;

    float q[4][4], k[4][4], v[4][4];
#pragma unroll
    for (int r = 0; r < RR; r++) {
        const float* base = qkv + ((size_t)r * NN + n) * (3 * DD) + h * 128 + lane;
#pragma unroll
        for (int e = 0; e < 4; e++) {
            q[r][e] = base[32 * e];
            k[r][e] = base[256 + 32 * e];
            v[r][e] = base[512 + 32 * e];
        }
    }
    float s[4][4];
#pragma unroll
    for (int a = 0; a < 4; a++)
#pragma unroll
        for (int b = 0; b < 4; b++) {
            float p = 0.f;
#pragma unroll
            for (int e = 0; e < 4; e++) p = fmaf(q[a][e], k[b][e], p);
            s[a][b] = warp_sum(p) * 0.08838834764831845f;  // 1/sqrt(128)
        }
    float o[4][4];
#pragma unroll
    for (int a = 0; a < 4; a++)
#pragma unroll
        for (int e = 0; e < 4; e++) o[a][e] = 0.f;
#pragma unroll
    for (int a = 0; a < 4; a++) {
        float m = fmaxf(fmaxf(s[a][0], s[a][1]), fmaxf(s[a][2], s[a][3]));
        float p[4]; float sum = 0.f;
#pragma unroll
        for (int b = 0; b < 4; b++) { p[b] = expf(s[a][b] - m); sum += p[b]; }
        float inv = 1.f / sum;
#pragma unroll
        for (int b = 0; b < 4; b++) {
            float wgt = p[b] * inv;
#pragma unroll
            for (int e = 0; e < 4; e++) o[a][e] = fmaf(wgt, v[b][e], o[a][e]);
        }
    }
#pragma unroll
    for (int a = 0; a < 4; a++) {
        float* dst = oat + ((size_t)a * NN + n) * DD + h * 128 + lane;
#pragma unroll
        for (int e = 0; e < 4; e++) dst[32 * e] = o[a][e];
    }
}

// ---------------- LayerNorm(A+B) per row, warp per row -----------------------
__global__ void ln_add_kernel(const float* __restrict__ A, const float* __restrict__ Bv,
                              const float* __restrict__ g, const float* __restrict__ bb,
                              float* __restrict__ out, size_t rows)
{
    size_t gt = (size_t)blockIdx.x * blockDim.x + threadIdx.x;
    size_t w  = gt >> 5;
    int lane  = threadIdx.x & 31;
    if (w >= rows) return;
    const float* pa = A + w * DD;
    const float* pb = Bv + w * DD;
    float y[8]; float s = 0.f;
#pragma unroll
    for (int e = 0; e < 8; e++) { int d = lane + 32 * e; y[e] = pa[d] + pb[d]; s += y[e]; }
    s = warp_sum(s);
    float mean = s * (1.f / DD);
    float vs = 0.f;
#pragma unroll
    for (int e = 0; e < 8; e++) { float dv = y[e] - mean; vs += dv * dv; }
    vs = warp_sum(vs);
    float inv = rsqrtf(vs * (1.f / DD) + 1e-5f);
    float* po = out + w * DD;
#pragma unroll
    for (int e = 0; e < 8; e++) {
        int d = lane + 32 * e;
        po[d] = (y[e] - mean) * inv * g[d] + bb[d];
    }
}

// ---------------- final: mean over R of LN(x1+ff2), warp per node ------------
__global__ void final_kernel(const float* __restrict__ x1, const float* __restrict__ ff2,
                             const float* __restrict__ g, const float* __restrict__ bb,
                             float* __restrict__ out)
{
    size_t gt = (size_t)blockIdx.x * blockDim.x + threadIdx.x;
    size_t n  = gt >> 5;
    int lane  = threadIdx.x & 31;
    if (n >= NN) return;
    float acc[8];
#pragma unroll
    for (int e = 0; e < 8; e++) acc[e] = 0.f;
    for (int r = 0; r < RR; r++) {
        size_t off = ((size_t)r * NN + n) * DD;
        float y[8]; float s = 0.f;
#pragma unroll
        for (int e = 0; e < 8; e++) {
            int d = lane + 32 * e;
            y[e] = x1[off + d] + ff2[off + d];
            s += y[e];
        }
        s = warp_sum(s);
        float mean = s * (1.f / DD);
        float vs = 0.f;
#pragma unroll
        for (int e = 0; e < 8; e++) { float dv = y[e] - mean; vs += dv * dv; }
        vs = warp_sum(vs);
        float inv = rsqrtf(vs * (1.f / DD) + 1e-5f);
#pragma unroll
        for (int e = 0; e < 8; e++) {
            int d = lane + 32 * e;
            acc[e] += (y[e] - mean) * inv * g[d] + bb[d];
        }
    }
#pragma unroll
    for (int e = 0; e < 8; e++) out[n * DD + lane + 32 * e] = acc[e] * 0.25f;
}

// ---------------- launch ------------------------------------------------------
extern "C" void kernel_launch(void* const* d_in, const int* in_sizes, int n_in,
                              void* d_out, int out_size)
{
    const float* x     = (const float*)d_in[0];
    const int*   tris  = (const int*)  d_in[1];
    // d_in[2] = edge_index (unused)
    const float* nodeW = (const float*)d_in[3];
    const float* triW  = (const float*)d_in[4];
    const float* resW  = (const float*)d_in[5];
    const float* gateW = (const float*)d_in[6];
    const float* gateB = (const float*)d_in[7];
    const float* inW   = (const float*)d_in[8];
    const float* inB   = (const float*)d_in[9];
    const float* outW  = (const float*)d_in[10];
    const float* outB  = (const float*)d_in[11];
    const float* ln1g  = (const float*)d_in[12];
    const float* ln1b  = (const float*)d_in[13];
    const float* lin1W = (const float*)d_in[14];
    const float* lin1b = (const float*)d_in[15];
    const float* lin2W = (const float*)d_in[16];
    const float* lin2b = (const float*)d_in[17];
    const float* ln2g  = (const float*)d_in[18];
    const float* ln2b  = (const float*)d_in[19];
    float* out = (float*)d_out;

    float* arena;
    float* comb;
    cudaGetSymbolAddress((void**)&arena, g_arena);
    cudaGetSymbolAddress((void**)&comb,  g_comb);

    // ---- aliased buffer map ----
    float* src   = arena;               // [0, RND)
    float* big   = arena + RND;         // [RND, 4*RND) = 12*ND
    float* t2    = arena + 4 * RND;     // [4*RND, 5*RND)
    float* xres  = big;                 // ND
    float* u     = big + ND;            // ND
    float* glog1 = big + 2 * ND;        // ND (relation-invariant gate part)
    float* glog2 = big + 3 * ND;        // ND
    float* nmsg  = big + 4 * ND;        // ND
    float* tmsg  = big + 5 * ND;        // 1.5*ND (TT*DD)
    float* cnt   = big + 7 * ND;        // NN floats
    float* qkv   = big;                 // 3*RND
    float* oattn = t2;                  // RND
    float* oproj = big;                 // RND (qkv dead after attn)
    float* x1    = src;                 // in-place LN over src+oproj
    float* ff1   = big;                 // 2*RND (oproj dead after ln_add)
    float* ff2   = t2;                  // RND (oattn dead)

    dim3 blk(256);

    combw_kernel<<<dim3(16, 16, RR), dim3(16, 16)>>>(nodeW, triW, comb);

    gemm_tc<0, 0><<<dim3(782, 2), blk>>>(x, resW, xres, nullptr, nullptr, 0,
                                         NN, DD, DD, DD, DD);
    gemm_tc<0, 0><<<dim3(782, 2), blk>>>(x, gateW, glog1, gateB, nullptr, 0,
                                         NN, DD, DD, 2 * DD, DD);

    for (int r = 0; r < RR; r++) {
        const int* trir = tris + (size_t)r * 3 * TT;
        cudaMemsetAsync(nmsg, 0, ND * sizeof(float), 0);
        cudaMemsetAsync(cnt, 0, (size_t)NN * sizeof(float), 0);
        gemm_tc<1, 0><<<dim3(1172, 2), blk>>>(x, comb + (size_t)r * DD * DD,
                                              tmsg, nullptr, trir, TT,
                                              TT, DD, DD, DD, DD);
        scatter_kernel<<<18750, blk>>>(tmsg, trir, nmsg, cnt);
        u_kernel<<<(unsigned)(ND / 256), blk>>>(nmsg, cnt, u);
        gemm_tc<0, 0><<<dim3(782, 2), blk>>>(u, gateW + DD, glog2, nullptr, nullptr, 0,
                                             NN, DD, DD, 2 * DD, DD);
        h_kernel<<<(unsigned)(ND / 256), blk>>>(u, glog1, glog2, xres, src + (size_t)r * ND);
    }

    gemm_tc<0, 0><<<dim3(3125, 6), blk>>>(src, inW, qkv, inB, nullptr, 0,
                                          RR * NN, DD, DD, DD, 3 * DD);
    attn_kernel<<<25000, blk>>>(qkv, oattn);
    gemm_tc<0, 0><<<dim3(3125, 2), blk>>>(oattn, outW, oproj, outB, nullptr, 0,
                                          RR * NN, DD, DD, DD, DD);
    ln_add_kernel<<<50000, blk>>>(src, oproj, ln1g, ln1b, x1, (size_t)RR * NN);
    gemm_tc<0, 1><<<dim3(3125, 4), blk>>>(x1, lin1W, ff1, lin1b, nullptr, 0,
                                          RR * NN, DD, DD, DD, 2 * DD);
    gemm_tc<0, 0><<<dim3(3125, 2), blk>>>(ff1, lin2W, ff2, lin2b, nullptr, 0,
                                          RR * NN, 2 * DD, 2 * DD, 2 * DD, DD);
    final_kernel<<<12500, blk>>>(x1, ff2, ln2g, ln2b, out);
}

// round 6
// speedup vs baseline: 2.1632x; 1.0655x over previous
#include <cuda_runtime.h>
#include <math.h>
#include <stddef.h>
#include <stdint.h>

#define NN 100000
#define DD 256
#define RR 4
#define TT 150000
#define HH 2

constexpr size_t ND  = (size_t)NN * DD;         // 25.6M floats
constexpr size_t RND = (size_t)RR * NN * DD;    // 102.4M floats

__device__ float g_arena[5 * RND];
__device__ float g_comb[(size_t)RR * DD * DD];

// ---------------- helpers ----------------------------------------------------
__device__ __forceinline__ float warp_sum(float v) {
#pragma unroll
    for (int o = 16; o; o >>= 1) v += __shfl_xor_sync(0xffffffffu, v, o);
    return v;
}
__device__ __forceinline__ float gelu_exact(float x) {
    return 0.5f * x * (1.0f + erff(x * 0.7071067811865475f));
}
__device__ __forceinline__ uint32_t f2tf32(float x) {
    uint32_t r;
    asm("cvt.rna.tf32.f32 %0, %1;" : "=r"(r) : "f"(x));
    return r;
}
__device__ __forceinline__ void mma_tf32(float& c0, float& c1, float& c2, float& c3,
                                         uint32_t a0, uint32_t a1, uint32_t a2, uint32_t a3,
                                         uint32_t b0, uint32_t b1) {
    asm volatile(
        "mma.sync.aligned.m16n8k8.row.col.f32.tf32.tf32.f32 "
        "{%0,%1,%2,%3}, {%4,%5,%6,%7}, {%8,%9}, {%0,%1,%2,%3};"
        : "+f"(c0), "+f"(c1), "+f"(c2), "+f"(c3)
        : "r"(a0), "r"(a1), "r"(a2), "r"(a3), "r"(b0), "r"(b1));
}

// ---------------- TF32 tensor-core GEMM: C[M,Nc] = A[M,K] @ B[Nc,K]^T --------
// Fragment-major smem layout: per-thread MMA fragments are contiguous
// swizzled granules -> A frag = 1x LDS.128, B frag = 1x LDS.64 (conflict-free).
// Double-buffered, register prefetch, 1 sync per K-iteration.
// TRIA: A rows are gathered means of 3 x-rows per triangle index.
#define BM 128
#define BN 128
#define BK 16

// A layout: block (mb = m>>4, kb = k>>3) of 128 words.
//   granule = (m&7)*4 + (((k&3) + (m&7)) & 3)    (16B granule, permuted)
//   word    = granule*4 + ((m>>3)&1) + ((k>>2)&1)*2
__device__ __forceinline__ int a_off(int m, int k) {
    int g = m & 7;
    return ((m >> 4) * 2 + (k >> 3)) * 128
         + (g * 4 + (((k & 3) + g) & 3)) * 4
         + ((m >> 3) & 1) + ((k >> 2) & 1) * 2;
}
// B layout: block (nb = n>>3, kb = k>>3) of 64 words.
//   granule = (n&7)*4 + (((k&3) + (n&7)) & 3)    (8B granule)
//   word    = granule*2 + ((k>>2)&1)
__device__ __forceinline__ int b_off(int n, int k) {
    int g = n & 7;
    return ((n >> 3) * 2 + (k >> 3)) * 64
         + (g * 4 + (((k & 3) + g) & 3)) * 2
         + ((k >> 2) & 1);
}

template <int TRIA, int ACT>
__global__ __launch_bounds__(256, 2)
void gemm_tc(const float* __restrict__ A, const float* __restrict__ B,
             float* __restrict__ C, const float* __restrict__ bias,
             const int* __restrict__ tri, int triN,
             int M, int K, int lda, int ldb, int ldc)
{
    __shared__ __align__(16) uint32_t As[2][BM * BK];
    __shared__ __align__(16) uint32_t Bs[2][BN * BK];
    const int t   = threadIdx.x;
    const int m0  = blockIdx.x * BM;
    const int n0  = blockIdx.y * BN;
    const int w   = t >> 5, lane = t & 31;
    const int wm  = w >> 2;          // 2 warps along M (64 rows each)
    const int wn  = w & 3;           // 4 warps along N (32 cols each)
    const int g   = lane >> 2;       // group id 0..7
    const int c4  = lane & 3;        // thread-in-group 0..3
    const int gran = g * 4 + ((c4 + g) & 3);   // permuted granule index

    // producer mapping: 4 threads per row, float4 each (two rounds: +0, +256)
    const int rowP = t >> 2;
    const int kqP  = (t & 3) << 2;

    float acc[4][4][4];
#pragma unroll
    for (int i = 0; i < 4; i++)
#pragma unroll
        for (int j = 0; j < 4; j++)
#pragma unroll
            for (int e = 0; e < 4; e++) acc[i][j][e] = 0.f;

    float4 pa[2], pb[2];

    auto ldg_tile = [&](int kk) {
#pragma unroll
        for (int qd = 0; qd < 2; qd++) {
            int row = rowP + qd * 64;
            float4 va = make_float4(0.f, 0.f, 0.f, 0.f);
            int gr = m0 + row;
            if (gr < M) {
                if (TRIA) {
                    int i0 = tri[gr], i1 = tri[triN + gr], i2 = tri[2 * triN + gr];
                    float4 a0 = *(const float4*)(A + (size_t)i0 * lda + kk + kqP);
                    float4 a1 = *(const float4*)(A + (size_t)i1 * lda + kk + kqP);
                    float4 a2 = *(const float4*)(A + (size_t)i2 * lda + kk + kqP);
                    const float third = 1.f / 3.f;
                    va.x = (a0.x + a1.x + a2.x) * third;
                    va.y = (a0.y + a1.y + a2.y) * third;
                    va.z = (a0.z + a1.z + a2.z) * third;
                    va.w = (a0.w + a1.w + a2.w) * third;
                } else {
                    va = *(const float4*)(A + (size_t)gr * lda + kk + kqP);
                }
            }
            pa[qd] = va;
            pb[qd] = *(const float4*)(B + (size_t)(n0 + row) * ldb + kk + kqP);
        }
    };
    auto sts_tile = [&](int st) {
#pragma unroll
        for (int qd = 0; qd < 2; qd++) {
            int row = rowP + qd * 64;
            const float va[4] = {pa[qd].x, pa[qd].y, pa[qd].z, pa[qd].w};
            const float vb[4] = {pb[qd].x, pb[qd].y, pb[qd].z, pb[qd].w};
#pragma unroll
            for (int j = 0; j < 4; j++) {
                As[st][a_off(row, kqP + j)] = f2tf32(va[j]);
                Bs[st][b_off(row, kqP + j)] = f2tf32(vb[j]);
            }
        }
    };

    ldg_tile(0);
    sts_tile(0);
    __syncthreads();

    int st = 0;
    for (int kk = 0; kk < K; kk += BK) {
        const bool more = (kk + BK) < K;
        if (more) ldg_tile(kk + BK);

#pragma unroll
        for (int kb = 0; kb < BK; kb += 8) {
            const int kbblk = kb >> 3;
            uint4 af[4];
#pragma unroll
            for (int mf = 0; mf < 4; mf++) {
                int mb = wm * 4 + mf;
                af[mf] = *(const uint4*)&As[st][(mb * 2 + kbblk) * 128 + gran * 4];
            }
#pragma unroll
            for (int nf = 0; nf < 4; nf++) {
                int nb = wn * 4 + nf;
                uint2 bf = *(const uint2*)&Bs[st][(nb * 2 + kbblk) * 64 + gran * 2];
#pragma unroll
                for (int mf = 0; mf < 4; mf++)
                    mma_tf32(acc[mf][nf][0], acc[mf][nf][1], acc[mf][nf][2], acc[mf][nf][3],
                             af[mf].x, af[mf].y, af[mf].z, af[mf].w, bf.x, bf.y);
            }
        }
        if (more) sts_tile(st ^ 1);
        __syncthreads();
        st ^= 1;
    }

    // --- epilogue ---
    const bool hb = (bias != nullptr);
#pragma unroll
    for (int mf = 0; mf < 4; mf++) {
#pragma unroll
        for (int half = 0; half < 2; half++) {
            int gm = m0 + wm * 64 + mf * 16 + g + half * 8;
            if (gm >= M) continue;
            float* cp = C + (size_t)gm * ldc + n0 + wn * 32;
#pragma unroll
            for (int nf = 0; nf < 4; nf++) {
                int col = nf * 8 + c4 * 2;
                float v0 = acc[mf][nf][half * 2 + 0];
                float v1 = acc[mf][nf][half * 2 + 1];
                if (hb) {
                    v0 += bias[n0 + wn * 32 + col];
                    v1 += bias[n0 + wn * 32 + col + 1];
                }
                if (ACT == 1) { v0 = gelu_exact(v0); v1 = gelu_exact(v1); }
                *(float2*)(cp + col) = make_float2(v0, v1);
            }
        }
    }
}

// ---------------- comb[r] = tri_W[r] @ node_W[r]  (tiny, fp32 SIMT) ----------
__global__ void combw_kernel(const float* __restrict__ nodeW,
                             const float* __restrict__ triW,
                             float* __restrict__ comb)
{
    __shared__ float Ts[16][16];
    __shared__ float Ns[16][17];
    int r  = blockIdx.z;
    int ii = blockIdx.y * 16 + threadIdx.y;
    int kk = blockIdx.x * 16 + threadIdx.x;
    const float* tw = triW  + (size_t)r * DD * DD;
    const float* nw = nodeW + (size_t)r * DD * DD;
    float s = 0.f;
    for (int j0 = 0; j0 < DD; j0 += 16) {
        Ts[threadIdx.y][threadIdx.x] = tw[(size_t)ii * DD + j0 + threadIdx.x];
        Ns[threadIdx.y][threadIdx.x] = nw[(size_t)(j0 + threadIdx.y) * DD + kk];
        __syncthreads();
#pragma unroll
        for (int j = 0; j < 16; j++) s = fmaf(Ts[threadIdx.y][j], Ns[j][threadIdx.x], s);
        __syncthreads();
    }
    comb[((size_t)r * DD + ii) * DD + kk] = s;
}

// ---------------- misc elementwise kernels -----------------------------------
__global__ void scatter_kernel(const float* __restrict__ tmsg,
                               const int* __restrict__ tri,
                               float* __restrict__ nmsg, float* __restrict__ cnt)
{
    int gw   = (int)(((size_t)blockIdx.x * blockDim.x + threadIdx.x) >> 5);
    int lane = threadIdx.x & 31;
    if (gw >= TT) return;
    int t0 = tri[gw], t1 = tri[TT + gw], t2 = tri[2 * TT + gw];
    const float* row = tmsg + (size_t)gw * DD;
    float v[8];
#pragma unroll
    for (int e = 0; e < 8; e++) v[e] = row[lane + 32 * e];
    float* p0 = nmsg + (size_t)t0 * DD;
    float* p1 = nmsg + (size_t)t1 * DD;
    float* p2 = nmsg + (size_t)t2 * DD;
#pragma unroll
    for (int e = 0; e < 8; e++) {
        int d = lane + 32 * e;
        atomicAdd(p0 + d, v[e]);
        atomicAdd(p1 + d, v[e]);
        atomicAdd(p2 + d, v[e]);
    }
    if (lane == 0) {
        atomicAdd(cnt + t0, 1.f);
        atomicAdd(cnt + t1, 1.f);
        atomicAdd(cnt + t2, 1.f);
    }
}

__global__ void u_kernel(const float* __restrict__ nmsg,
                         const float* __restrict__ cnt, float* __restrict__ u)
{
    size_t i = (size_t)blockIdx.x * blockDim.x + threadIdx.x;
    if (i >= ND) return;
    int n = (int)(i >> 8);
    float c = fmaxf(cnt[n], 1.f);
    float v = nmsg[i] / c;
    u[i] = v > 0.f ? v : expm1f(v);    // ELU(alpha=1)
}

__global__ void h_kernel(const float* __restrict__ u,
                         const float* __restrict__ glog1, const float* __restrict__ glog2,
                         const float* __restrict__ xres, float* __restrict__ dst)
{
    size_t i = (size_t)blockIdx.x * blockDim.x + threadIdx.x;
    if (i >= ND) return;
    float a = 1.f / (1.f + expf(-(glog1[i] + glog2[i])));
    dst[i] = tanhf(u[i]) * a + xres[i] * (1.f - a);
}

// ---------------- attention over relation axis (R=4): warp per (node, head) --
__global__ void attn_kernel(const float* __restrict__ qkv, float* __restrict__ oat)
{
    size_t gt = (size_t)blockIdx.x * blockDim.x + threadIdx.x;
    int gw   = (int)(gt >> 5);
    int lane = threadIdx.x & 31;
    if (gw >= NN * HH) return;
    int n = gw >> 1, h = gw & 1;

    float q[4][4], k[4][4], v[4][4];
#pragma unroll
    for (int r = 0; r < RR; r++) {
        const float* base = qkv + ((size_t)r * NN + n) * (3 * DD) + h * 128 + lane;
#pragma unroll
        for (int e = 0; e < 4; e++) {
            q[r][e] = base[32 * e];
            k[r][e] = base[256 + 32 * e];
            v[r][e] = base[512 + 32 * e];
        }
    }
    float s[4][4];
#pragma unroll
    for (int a = 0; a < 4; a++)
#pragma unroll
        for (int b = 0; b < 4; b++) {
            float p = 0.f;
#pragma unroll
            for (int e = 0; e < 4; e++) p = fmaf(q[a][e], k[b][e], p);
            s[a][b] = warp_sum(p) * 0.08838834764831845f;  // 1/sqrt(128)
        }
    float o[4][4];
#pragma unroll
    for (int a = 0; a < 4; a++)
#pragma unroll
        for (int e = 0; e < 4; e++) o[a][e] = 0.f;
#pragma unroll
    for (int a = 0; a < 4; a++) {
        float m = fmaxf(fmaxf(s[a][0], s[a][1]), fmaxf(s[a][2], s[a][3]));
        float p[4]; float sum = 0.f;
#pragma unroll
        for (int b = 0; b < 4; b++) { p[b] = expf(s[a][b] - m); sum += p[b]; }
        float inv = 1.f / sum;
#pragma unroll
        for (int b = 0; b < 4; b++) {
            float wgt = p[b] * inv;
#pragma unroll
            for (int e = 0; e < 4; e++) o[a][e] = fmaf(wgt, v[b][e], o[a][e]);
        }
    }
#pragma unroll
    for (int a = 0; a < 4; a++) {
        float* dst = oat + ((size_t)a * NN + n) * DD + h * 128 + lane;
#pragma unroll
        for (int e = 0; e < 4; e++) dst[32 * e] = o[a][e];
    }
}

// ---------------- LayerNorm(A+B) per row, warp per row -----------------------
__global__ void ln_add_kernel(const float* __restrict__ A, const float* __restrict__ Bv,
                              const float* __restrict__ g, const float* __restrict__ bb,
                              float* __restrict__ out, size_t rows)
{
    size_t gt = (size_t)blockIdx.x * blockDim.x + threadIdx.x;
    size_t w  = gt >> 5;
    int lane  = threadIdx.x & 31;
    if (w >= rows) return;
    const float* pa = A + w * DD;
    const float* pb = Bv + w * DD;
    float y[8]; float s = 0.f;
#pragma unroll
    for (int e = 0; e < 8; e++) { int d = lane + 32 * e; y[e] = pa[d] + pb[d]; s += y[e]; }
    s = warp_sum(s);
    float mean = s * (1.f / DD);
    float vs = 0.f;
#pragma unroll
    for (int e = 0; e < 8; e++) { float dv = y[e] - mean; vs += dv * dv; }
    vs = warp_sum(vs);
    float inv = rsqrtf(vs * (1.f / DD) + 1e-5f);
    float* po = out + w * DD;
#pragma unroll
    for (int e = 0; e < 8; e++) {
        int d = lane + 32 * e;
        po[d] = (y[e] - mean) * inv * g[d] + bb[d];
    }
}

// ---------------- final: mean over R of LN(x1+ff2), warp per node ------------
__global__ void final_kernel(const float* __restrict__ x1, const float* __restrict__ ff2,
                             const float* __restrict__ g, const float* __restrict__ bb,
                             float* __restrict__ out)
{
    size_t gt = (size_t)blockIdx.x * blockDim.x + threadIdx.x;
    size_t n  = gt >> 5;
    int lane  = threadIdx.x & 31;
    if (n >= NN) return;
    float acc[8];
#pragma unroll
    for (int e = 0; e < 8; e++) acc[e] = 0.f;
    for (int r = 0; r < RR; r++) {
        size_t off = ((size_t)r * NN + n) * DD;
        float y[8]; float s = 0.f;
#pragma unroll
        for (int e = 0; e < 8; e++) {
            int d = lane + 32 * e;
            y[e] = x1[off + d] + ff2[off + d];
            s += y[e];
        }
        s = warp_sum(s);
        float mean = s * (1.f / DD);
        float vs = 0.f;
#pragma unroll
        for (int e = 0; e < 8; e++) { float dv = y[e] - mean; vs += dv * dv; }
        vs = warp_sum(vs);
        float inv = rsqrtf(vs * (1.f / DD) + 1e-5f);
#pragma unroll
        for (int e = 0; e < 8; e++) {
            int d = lane + 32 * e;
            acc[e] += (y[e] - mean) * inv * g[d] + bb[d];
        }
    }
#pragma unroll
    for (int e = 0; e < 8; e++) out[n * DD + lane + 32 * e] = acc[e] * 0.25f;
}

// ---------------- launch ------------------------------------------------------
extern "C" void kernel_launch(void* const* d_in, const int* in_sizes, int n_in,
                              void* d_out, int out_size)
{
    const float* x     = (const float*)d_in[0];
    const int*   tris  = (const int*)  d_in[1];
    // d_in[2] = edge_index (unused)
    const float* nodeW = (const float*)d_in[3];
    const float* triW  = (const float*)d_in[4];
    const float* resW  = (const float*)d_in[5];
    const float* gateW = (const float*)d_in[6];
    const float* gateB = (const float*)d_in[7];
    const float* inW   = (const float*)d_in[8];
    const float* inB   = (const float*)d_in[9];
    const float* outW  = (const float*)d_in[10];
    const float* outB  = (const float*)d_in[11];
    const float* ln1g  = (const float*)d_in[12];
    const float* ln1b  = (const float*)d_in[13];
    const float* lin1W = (const float*)d_in[14];
    const float* lin1b = (const float*)d_in[15];
    const float* lin2W = (const float*)d_in[16];
    const float* lin2b = (const float*)d_in[17];
    const float* ln2g  = (const float*)d_in[18];
    const float* ln2b  = (const float*)d_in[19];
    float* out = (float*)d_out;

    float* arena;
    float* comb;
    cudaGetSymbolAddress((void**)&arena, g_arena);
    cudaGetSymbolAddress((void**)&comb,  g_comb);

    float* src   = arena;
    float* big   = arena + RND;
    float* t2    = arena + 4 * RND;
    float* xres  = big;
    float* u     = big + ND;
    float* glog1 = big + 2 * ND;
    float* glog2 = big + 3 * ND;
    float* nmsg  = big + 4 * ND;
    float* tmsg  = big + 5 * ND;
    float* cnt   = big + 7 * ND;
    float* qkv   = big;
    float* oattn = t2;
    float* oproj = big;
    float* x1    = src;
    float* ff1   = big;
    float* ff2   = t2;

    dim3 blk(256);

    combw_kernel<<<dim3(16, 16, RR), dim3(16, 16)>>>(nodeW, triW, comb);

    gemm_tc<0, 0><<<dim3(782, 2), blk>>>(x, resW, xres, nullptr, nullptr, 0,
                                         NN, DD, DD, DD, DD);
    gemm_tc<0, 0><<<dim3(782, 2), blk>>>(x, gateW, glog1, gateB, nullptr, 0,
                                         NN, DD, DD, 2 * DD, DD);

    for (int r = 0; r < RR; r++) {
        const int* trir = tris + (size_t)r * 3 * TT;
        cudaMemsetAsync(nmsg, 0, ND * sizeof(float), 0);
        cudaMemsetAsync(cnt, 0, (size_t)NN * sizeof(float), 0);
        gemm_tc<1, 0><<<dim3(1172, 2), blk>>>(x, comb + (size_t)r * DD * DD,
                                              tmsg, nullptr, trir, TT,
                                              TT, DD, DD, DD, DD);
        scatter_kernel<<<18750, blk>>>(tmsg, trir, nmsg, cnt);
        u_kernel<<<(unsigned)(ND / 256), blk>>>(nmsg, cnt, u);
        gemm_tc<0, 0><<<dim3(782, 2), blk>>>(u, gateW + DD, glog2, nullptr, nullptr, 0,
                                             NN, DD, DD, 2 * DD, DD);
        h_kernel<<<(unsigned)(ND / 256), blk>>>(u, glog1, glog2, xres, src + (size_t)r * ND);
    }

    gemm_tc<0, 0><<<dim3(3125, 6), blk>>>(src, inW, qkv, inB, nullptr, 0,
                                          RR * NN, DD, DD, DD, 3 * DD);
    attn_kernel<<<25000, blk>>>(qkv, oattn);
    gemm_tc<0, 0><<<dim3(3125, 2), blk>>>(oattn, outW, oproj, outB, nullptr, 0,
                                          RR * NN, DD, DD, DD, DD);
    ln_add_kernel<<<50000, blk>>>(src, oproj, ln1g, ln1b, x1, (size_t)RR * NN);
    gemm_tc<0, 1><<<dim3(3125, 4), blk>>>(x1, lin1W, ff1, lin1b, nullptr, 0,
                                          RR * NN, DD, DD, DD, 2 * DD);
    gemm_tc<0, 0><<<dim3(3125, 2), blk>>>(ff1, lin2W, ff2, lin2b, nullptr, 0,
                                          RR * NN, 2 * DD, 2 * DD, 2 * DD, DD);
    final_kernel<<<12500, blk>>>(x1, ff2, ln2g, ln2b, out);
}

// round 7
// speedup vs baseline: 2.5354x; 1.1721x over previous
#include <cuda_runtime.h>
#include <math.h>
#include <stddef.h>
#include <stdint.h>

#define NN 100000
#define DD 256
#define RR 4
#define TT 150000
#define HH 2

constexpr size_t ND  = (size_t)NN * DD;         // 25.6M floats
constexpr size_t RND = (size_t)RR * NN * DD;    // 102.4M floats

__device__ float g_arena[5 * RND];
__device__ float g_comb[(size_t)RR * DD * DD];
// rounded weight copies: resW | gateW | inW | outW | lin1W | lin2W
__device__ float g_wrt[65536 + 131072 + 196608 + 65536 + 131072 + 131072];

// ---------------- helpers ----------------------------------------------------
__device__ __forceinline__ float warp_sum(float v) {
#pragma unroll
    for (int o = 16; o; o >>= 1) v += __shfl_xor_sync(0xffffffffu, v, o);
    return v;
}
__device__ __forceinline__ float gelu_exact(float x) {
    return 0.5f * x * (1.0f + erff(x * 0.7071067811865475f));
}
__device__ __forceinline__ uint32_t f2tf32(float x) {
    uint32_t r;
    asm("cvt.rna.tf32.f32 %0, %1;" : "=r"(r) : "f"(x));
    return r;
}
__device__ __forceinline__ float rnd_tf32(float x) {
    return __uint_as_float(f2tf32(x));
}
__device__ __forceinline__ uint32_t sm2u32(const void* p) {
    uint32_t a;
    asm("{ .reg .u64 t; cvta.to.shared.u64 t, %1; cvt.u32.u64 %0, t; }"
        : "=r"(a) : "l"(p));
    return a;
}
__device__ __forceinline__ void mma_tf32(float& c0, float& c1, float& c2, float& c3,
                                         uint32_t a0, uint32_t a1, uint32_t a2, uint32_t a3,
                                         uint32_t b0, uint32_t b1) {
    asm volatile(
        "mma.sync.aligned.m16n8k8.row.col.f32.tf32.tf32.f32 "
        "{%0,%1,%2,%3}, {%4,%5,%6,%7}, {%8,%9}, {%0,%1,%2,%3};"
        : "+f"(c0), "+f"(c1), "+f"(c2), "+f"(c3)
        : "r"(a0), "r"(a1), "r"(a2), "r"(a3), "r"(b0), "r"(b1));
}
__device__ __forceinline__ void cp16(uint32_t dst, const void* src, uint32_t sz) {
    asm volatile("cp.async.cg.shared.global [%0], [%1], 16, %2;"
                 :: "r"(dst), "l"(src), "r"(sz) : "memory");
}

// ---------------- TF32 GEMM: C[M,Nc] = A[M,K] @ B[Nc,K]^T --------------------
// 4-stage cp.async pipeline (inputs pre-rounded to tf32), 80B-pitch skewed smem
// (conflict-free fragment LDS). TRIA: A rows = gathered mean of 3 x-rows,
// register path with cvt. ACT: GELU epilogue. ROUND: round output to tf32.
#define BM 128
#define BN 128
#define BK 16
#define NSTG 4
#define A_BYTES 10240                 /* 128 rows * 80B */
#define STG_BYTES (2 * A_BYTES)
#define GEMM_SMEM (NSTG * STG_BYTES)  /* 80KB */

template <int TRIA, int ACT, int ROUND>
__global__ __launch_bounds__(256, 2)
void gemm_cp(const float* __restrict__ A, const float* __restrict__ B,
             float* __restrict__ C, const float* __restrict__ bias,
             const int* __restrict__ tri, int triN,
             int M, int K, int lda, int ldb, int ldc)
{
    extern __shared__ uint32_t smw[];
    const int tid  = threadIdx.x;
    const int m0   = blockIdx.x * BM;
    const int n0   = blockIdx.y * BN;
    const int w    = tid >> 5, lane = tid & 31;
    const int wm   = w >> 2;           // 2 warps along M
    const int wn   = w & 3;            // 4 warps along N
    const int g    = lane >> 2;
    const int c4   = lane & 3;
    const uint32_t sbase = sm2u32(smw);

    // producer granule coords (2 A-granules + 2 B-granules per thread)
    const int pm[2]  = { tid >> 2, (tid + 256) >> 2 };
    const int pkq[2] = { (tid & 3) * 4, (tid & 3) * 4 };

    // TRIA: hoist triangle indices for my 2 A-rows
    int ti0[2], ti1[2], ti2[2];
    if (TRIA) {
#pragma unroll
        for (int i = 0; i < 2; i++) {
            int gr = m0 + pm[i];
            int s = (gr < M) ? gr : 0;
            ti0[i] = tri[s]; ti1[i] = tri[triN + s]; ti2[i] = tri[2 * triN + s];
        }
    }

    float acc[4][4][4];
#pragma unroll
    for (int i = 0; i < 4; i++)
#pragma unroll
        for (int j = 0; j < 4; j++)
#pragma unroll
            for (int e = 0; e < 4; e++) acc[i][j][e] = 0.f;

    auto tria_mean = [&](int i, int kk) -> float4 {
        const float th = 1.f / 3.f;
        const float4 a0 = *(const float4*)(A + (size_t)ti0[i] * lda + kk + pkq[i]);
        const float4 a1 = *(const float4*)(A + (size_t)ti1[i] * lda + kk + pkq[i]);
        const float4 a2 = *(const float4*)(A + (size_t)ti2[i] * lda + kk + pkq[i]);
        return make_float4((a0.x + a1.x + a2.x) * th, (a0.y + a1.y + a2.y) * th,
                           (a0.z + a1.z + a2.z) * th, (a0.w + a1.w + a2.w) * th);
    };
    auto sts_a = [&](int st, int i, float4 v) {
        uint32_t dst = sbase + st * STG_BYTES + pm[i] * 80 + (pkq[i] / 4) * 16;
        asm volatile("st.shared.v4.b32 [%0], {%1,%2,%3,%4};"
                     :: "r"(dst), "r"(f2tf32(v.x)), "r"(f2tf32(v.y)),
                        "r"(f2tf32(v.z)), "r"(f2tf32(v.w)) : "memory");
    };
    auto issue_tile = [&](int ct) {
        const int st = ct & (NSTG - 1);
        const uint32_t sb = sbase + st * STG_BYTES;
        const int kk = ct << 4;
#pragma unroll
        for (int i = 0; i < 2; i++) {
            const uint32_t doff = pm[i] * 80 + (pkq[i] / 4) * 16;
            if (!TRIA) {
                int gr = m0 + pm[i];
                const float* sa = A + (size_t)((gr < M) ? gr : 0) * lda + kk + pkq[i];
                cp16(sb + doff, sa, (gr < M) ? 16u : 0u);
            }
            const float* sbp = B + (size_t)(n0 + pm[i]) * ldb + kk + pkq[i];
            cp16(sb + A_BYTES + doff, sbp, 16u);
        }
    };

    const int nt = K >> 4;
    // ---- prologue: stages 0..2 ----
#pragma unroll
    for (int ct = 0; ct < NSTG - 1; ct++) {
        if (TRIA) {
            float4 v0 = tria_mean(0, ct << 4);
            float4 v1 = tria_mean(1, ct << 4);
            sts_a(ct, 0, v0); sts_a(ct, 1, v1);
        }
        issue_tile(ct);
        asm volatile("cp.async.commit_group;" ::: "memory");
    }

    for (int c = 0; c < nt; c++) {
        const int st = c & (NSTG - 1);
        float4 tv0, tv1;
        const bool more = (c + NSTG - 1) < nt;
        if (TRIA && more) {                 // LDG early, overlaps wait
            tv0 = tria_mean(0, (c + NSTG - 1) << 4);
            tv1 = tria_mean(1, (c + NSTG - 1) << 4);
        }
        asm volatile("cp.async.wait_group %0;" :: "n"(NSTG - 2) : "memory");
        __syncthreads();
        if (more) {
            const int wst = (c + NSTG - 1) & (NSTG - 1);
            if (TRIA) { sts_a(wst, 0, tv0); sts_a(wst, 1, tv1); }
            issue_tile(c + NSTG - 1);
        }
        asm volatile("cp.async.commit_group;" ::: "memory");

        const uint32_t* sA = smw + st * (STG_BYTES / 4);
        const uint32_t* sB = sA + (A_BYTES / 4);
#pragma unroll
        for (int kb = 0; kb < BK; kb += 8) {
            uint32_t af[4][4];
#pragma unroll
            for (int mf = 0; mf < 4; mf++) {
                const int mi = (wm * 64 + mf * 16 + g) * 20 + kb + c4;
                af[mf][0] = sA[mi];       af[mf][1] = sA[mi + 160];
                af[mf][2] = sA[mi + 4];   af[mf][3] = sA[mi + 164];
            }
#pragma unroll
            for (int nf = 0; nf < 4; nf++) {
                const int ni = (wn * 32 + nf * 8 + g) * 20 + kb + c4;
                const uint32_t b0 = sB[ni];
                const uint32_t b1 = sB[ni + 4];
#pragma unroll
                for (int mf = 0; mf < 4; mf++)
                    mma_tf32(acc[mf][nf][0], acc[mf][nf][1], acc[mf][nf][2], acc[mf][nf][3],
                             af[mf][0], af[mf][1], af[mf][2], af[mf][3], b0, b1);
            }
        }
    }

    // --- epilogue ---
    const bool hb = (bias != nullptr);
#pragma unroll
    for (int mf = 0; mf < 4; mf++) {
#pragma unroll
        for (int half = 0; half < 2; half++) {
            int gm = m0 + wm * 64 + mf * 16 + g + half * 8;
            if (gm >= M) continue;
            float* cp = C + (size_t)gm * ldc + n0 + wn * 32;
#pragma unroll
            for (int nf = 0; nf < 4; nf++) {
                int col = nf * 8 + c4 * 2;
                float v0 = acc[mf][nf][half * 2 + 0];
                float v1 = acc[mf][nf][half * 2 + 1];
                if (hb) {
                    v0 += bias[n0 + wn * 32 + col];
                    v1 += bias[n0 + wn * 32 + col + 1];
                }
                if (ACT == 1) { v0 = gelu_exact(v0); v1 = gelu_exact(v1); }
                if (ROUND == 1) { v0 = rnd_tf32(v0); v1 = rnd_tf32(v1); }
                *(float2*)(cp + col) = make_float2(v0, v1);
            }
        }
    }
}

// ---------------- comb[r] = rna(tri_W[r] @ node_W[r]) ------------------------
__global__ void combw_kernel(const float* __restrict__ nodeW,
                             const float* __restrict__ triW,
                             float* __restrict__ comb)
{
    __shared__ float Ts[16][16];
    __shared__ float Ns[16][17];
    int r  = blockIdx.z;
    int ii = blockIdx.y * 16 + threadIdx.y;
    int kk = blockIdx.x * 16 + threadIdx.x;
    const float* tw = triW  + (size_t)r * DD * DD;
    const float* nw = nodeW + (size_t)r * DD * DD;
    float s = 0.f;
    for (int j0 = 0; j0 < DD; j0 += 16) {
        Ts[threadIdx.y][threadIdx.x] = tw[(size_t)ii * DD + j0 + threadIdx.x];
        Ns[threadIdx.y][threadIdx.x] = nw[(size_t)(j0 + threadIdx.y) * DD + kk];
        __syncthreads();
#pragma unroll
        for (int j = 0; j < 16; j++) s = fmaf(Ts[threadIdx.y][j], Ns[j][threadIdx.x], s);
        __syncthreads();
    }
    comb[((size_t)r * DD + ii) * DD + kk] = rnd_tf32(s);
}

// ---------------- rounding copy ----------------------------------------------
__global__ void round_kernel(const float* __restrict__ src, float* __restrict__ dst,
                             size_t n) {
    size_t i = (size_t)blockIdx.x * blockDim.x + threadIdx.x;
    if (i < n) dst[i] = rnd_tf32(src[i]);
}

// ---------------- misc elementwise kernels -----------------------------------
__global__ void scatter_kernel(const float* __restrict__ tmsg,
                               const int* __restrict__ tri,
                               float* __restrict__ nmsg, float* __restrict__ cnt)
{
    int gw   = (int)(((size_t)blockIdx.x * blockDim.x + threadIdx.x) >> 5);
    int lane = threadIdx.x & 31;
    if (gw >= TT) return;
    int t0 = tri[gw], t1 = tri[TT + gw], t2 = tri[2 * TT + gw];
    const float* row = tmsg + (size_t)gw * DD;
    float v[8];
#pragma unroll
    for (int e = 0; e < 8; e++) v[e] = row[lane + 32 * e];
    float* p0 = nmsg + (size_t)t0 * DD;
    float* p1 = nmsg + (size_t)t1 * DD;
    float* p2 = nmsg + (size_t)t2 * DD;
#pragma unroll
    for (int e = 0; e < 8; e++) {
        int d = lane + 32 * e;
        atomicAdd(p0 + d, v[e]);
        atomicAdd(p1 + d, v[e]);
        atomicAdd(p2 + d, v[e]);
    }
    if (lane == 0) {
        atomicAdd(cnt + t0, 1.f);
        atomicAdd(cnt + t1, 1.f);
        atomicAdd(cnt + t2, 1.f);
    }
}

__global__ void u_kernel(const float* __restrict__ nmsg,
                         const float* __restrict__ cnt, float* __restrict__ u)
{
    size_t i = (size_t)blockIdx.x * blockDim.x + threadIdx.x;
    if (i >= ND) return;
    int n = (int)(i >> 8);
    float c = fmaxf(cnt[n], 1.f);
    float v = nmsg[i] / c;
    u[i] = rnd_tf32(v > 0.f ? v : expm1f(v));    // ELU, tf32-rounded
}

__global__ void h_kernel(const float* __restrict__ u,
                         const float* __restrict__ glog1, const float* __restrict__ glog2,
                         const float* __restrict__ xres, float* __restrict__ dst)
{
    size_t i = (size_t)blockIdx.x * blockDim.x + threadIdx.x;
    if (i >= ND) return;
    float a = 1.f / (1.f + expf(-(glog1[i] + glog2[i])));
    dst[i] = rnd_tf32(tanhf(u[i]) * a + xres[i] * (1.f - a));
}

// ---------------- attention over relation axis (R=4): warp per (node, head) --
__global__ void attn_kernel(const float* __restrict__ qkv, float* __restrict__ oat)
{
    size_t gt = (size_t)blockIdx.x * blockDim.x + threadIdx.x;
    int gw   = (int)(gt >> 5);
    int lane = threadIdx.x & 31;
    if (gw >= NN * HH) return;
    int n = gw >> 1, h = gw & 1;

    float q[4][4], k[4][4], v[4][4];
#pragma unroll
    for (int r = 0; r < RR; r++) {
        const float* base = qkv + ((size_t)r * NN + n) * (3 * DD) + h * 128 + lane;
#pragma unroll
        for (int e = 0; e < 4; e++) {
            q[r][e] = base[32 * e];
            k[r][e] = base[256 + 32 * e];
            v[r][e] = base[512 + 32 * e];
        }
    }
    float s[4][4];
#pragma unroll
    for (int a = 0; a < 4; a++)
#pragma unroll
        for (int b = 0; b < 4; b++) {
            float p = 0.f;
#pragma unroll
            for (int e = 0; e < 4; e++) p = fmaf(q[a][e], k[b][e], p);
            s[a][b] = warp_sum(p) * 0.08838834764831845f;  // 1/sqrt(128)
        }
    float o[4][4];
#pragma unroll
    for (int a = 0; a < 4; a++)
#pragma unroll
        for (int e = 0; e < 4; e++) o[a][e] = 0.f;
#pragma unroll
    for (int a = 0; a < 4; a++) {
        float m = fmaxf(fmaxf(s[a][0], s[a][1]), fmaxf(s[a][2], s[a][3]));
        float p[4]; float sum = 0.f;
#pragma unroll
        for (int b = 0; b < 4; b++) { p[b] = expf(s[a][b] - m); sum += p[b]; }
        float inv = 1.f / sum;
#pragma unroll
        for (int b = 0; b < 4; b++) {
            float wgt = p[b] * inv;
#pragma unroll
            for (int e = 0; e < 4; e++) o[a][e] = fmaf(wgt, v[b][e], o[a][e]);
        }
    }
#pragma unroll
    for (int a = 0; a < 4; a++) {
        float* dst = oat + ((size_t)a * NN + n) * DD + h * 128 + lane;
#pragma unroll
        for (int e = 0; e < 4; e++) dst[32 * e] = rnd_tf32(o[a][e]);
    }
}

// ---------------- LayerNorm(A+B) per row, warp per row (tf32-rounded out) ----
__global__ void ln_add_kernel(const float* __restrict__ A, const float* __restrict__ Bv,
                              const float* __restrict__ g, const float* __restrict__ bb,
                              float* __restrict__ out, size_t rows)
{
    size_t gt = (size_t)blockIdx.x * blockDim.x + threadIdx.x;
    size_t w  = gt >> 5;
    int lane  = threadIdx.x & 31;
    if (w >= rows) return;
    const float* pa = A + w * DD;
    const float* pb = Bv + w * DD;
    float y[8]; float s = 0.f;
#pragma unroll
    for (int e = 0; e < 8; e++) { int d = lane + 32 * e; y[e] = pa[d] + pb[d]; s += y[e]; }
    s = warp_sum(s);
    float mean = s * (1.f / DD);
    float vs = 0.f;
#pragma unroll
    for (int e = 0; e < 8; e++) { float dv = y[e] - mean; vs += dv * dv; }
    vs = warp_sum(vs);
    float inv = rsqrtf(vs * (1.f / DD) + 1e-5f);
    float* po = out + w * DD;
#pragma unroll
    for (int e = 0; e < 8; e++) {
        int d = lane + 32 * e;
        po[d] = rnd_tf32((y[e] - mean) * inv * g[d] + bb[d]);
    }
}

// ---------------- final: mean over R of LN(x1+ff2), warp per node ------------
__global__ void final_kernel(const float* __restrict__ x1, const float* __restrict__ ff2,
                             const float* __restrict__ g, const float* __restrict__ bb,
                             float* __restrict__ out)
{
    size_t gt = (size_t)blockIdx.x * blockDim.x + threadIdx.x;
    size_t n  = gt >> 5;
    int lane  = threadIdx.x & 31;
    if (n >= NN) return;
    float acc[8];
#pragma unroll
    for (int e = 0; e < 8; e++) acc[e] = 0.f;
    for (int r = 0; r < RR; r++) {
        size_t off = ((size_t)r * NN + n) * DD;
        float y[8]; float s = 0.f;
#pragma unroll
        for (int e = 0; e < 8; e++) {
            int d = lane + 32 * e;
            y[e] = x1[off + d] + ff2[off + d];
            s += y[e];
        }
        s = warp_sum(s);
        float mean = s * (1.f / DD);
        float vs = 0.f;
#pragma unroll
        for (int e = 0; e < 8; e++) { float dv = y[e] - mean; vs += dv * dv; }
        vs = warp_sum(vs);
        float inv = rsqrtf(vs * (1.f / DD) + 1e-5f);
#pragma unroll
        for (int e = 0; e < 8; e++) {
            int d = lane + 32 * e;
            acc[e] += (y[e] - mean) * inv * g[d] + bb[d];
        }
    }
#pragma unroll
    for (int e = 0; e < 8; e++) out[n * DD + lane + 32 * e] = acc[e] * 0.25f;
}

// ---------------- launch ------------------------------------------------------
extern "C" void kernel_launch(void* const* d_in, const int* in_sizes, int n_in,
                              void* d_out, int out_size)
{
    const float* x     = (const float*)d_in[0];
    const int*   tris  = (const int*)  d_in[1];
    // d_in[2] = edge_index (unused)
    const float* nodeW = (const float*)d_in[3];
    const float* triW  = (const float*)d_in[4];
    const float* resW  = (const float*)d_in[5];
    const float* gateW = (const float*)d_in[6];
    const float* gateB = (const float*)d_in[7];
    const float* inW   = (const float*)d_in[8];
    const float* inB   = (const float*)d_in[9];
    const float* outW  = (const float*)d_in[10];
    const float* outB  = (const float*)d_in[11];
    const float* ln1g  = (const float*)d_in[12];
    const float* ln1b  = (const float*)d_in[13];
    const float* lin1W = (const float*)d_in[14];
    const float* lin1b = (const float*)d_in[15];
    const float* lin2W = (const float*)d_in[16];
    const float* lin2b = (const float*)d_in[17];
    const float* ln2g  = (const float*)d_in[18];
    const float* ln2b  = (const float*)d_in[19];
    float* out = (float*)d_out;

    float *arena, *comb, *wrt;
    cudaGetSymbolAddress((void**)&arena, g_arena);
    cudaGetSymbolAddress((void**)&comb,  g_comb);
    cudaGetSymbolAddress((void**)&wrt,   g_wrt);

    float* src   = arena;
    float* big   = arena + RND;
    float* t2    = arena + 4 * RND;
    float* xres  = big;
    float* u     = big + ND;
    float* glog1 = big + 2 * ND;
    float* glog2 = big + 3 * ND;
    float* nmsg  = big + 4 * ND;
    float* tmsg  = big + 5 * ND;
    float* cnt   = big + 7 * ND;
    float* x_rt  = big + 8 * ND;        // phase-A only (dead before qkv)
    float* qkv   = big;
    float* oattn = t2;
    float* oproj = big;
    float* x1    = src;
    float* ff1   = big;
    float* ff2   = t2;

    // rounded weights
    float* resW_rt  = wrt;
    float* gateW_rt = wrt + 65536;
    float* inW_rt   = gateW_rt + 131072;
    float* outW_rt  = inW_rt + 196608;
    float* lin1W_rt = outW_rt + 65536;
    float* lin2W_rt = lin1W_rt + 131072;

    cudaFuncSetAttribute(gemm_cp<0, 0, 0>, cudaFuncAttributeMaxDynamicSharedMemorySize, GEMM_SMEM);
    cudaFuncSetAttribute(gemm_cp<1, 0, 0>, cudaFuncAttributeMaxDynamicSharedMemorySize, GEMM_SMEM);
    cudaFuncSetAttribute(gemm_cp<0, 1, 1>, cudaFuncAttributeMaxDynamicSharedMemorySize, GEMM_SMEM);

    dim3 blk(256);

    // precompute rounded operands
    round_kernel<<<(unsigned)((ND + 255) / 256), blk>>>(x, x_rt, ND);
    round_kernel<<<256, blk>>>(resW,  resW_rt,  65536);
    round_kernel<<<512, blk>>>(gateW, gateW_rt, 131072);
    round_kernel<<<768, blk>>>(inW,   inW_rt,   196608);
    round_kernel<<<256, blk>>>(outW,  outW_rt,  65536);
    round_kernel<<<512, blk>>>(lin1W, lin1W_rt, 131072);
    round_kernel<<<512, blk>>>(lin2W, lin2W_rt, 131072);
    combw_kernel<<<dim3(16, 16, RR), dim3(16, 16)>>>(nodeW, triW, comb);

    gemm_cp<0, 0, 0><<<dim3(782, 2), blk, GEMM_SMEM>>>(x_rt, resW_rt, xres, nullptr,
                                                       nullptr, 0, NN, DD, DD, DD, DD);
    gemm_cp<0, 0, 0><<<dim3(782, 2), blk, GEMM_SMEM>>>(x_rt, gateW_rt, glog1, gateB,
                                                       nullptr, 0, NN, DD, DD, 2 * DD, DD);

    for (int r = 0; r < RR; r++) {
        const int* trir = tris + (size_t)r * 3 * TT;
        cudaMemsetAsync(nmsg, 0, ND * sizeof(float), 0);
        cudaMemsetAsync(cnt, 0, (size_t)NN * sizeof(float), 0);
        gemm_cp<1, 0, 0><<<dim3(1172, 2), blk, GEMM_SMEM>>>(x, comb + (size_t)r * DD * DD,
                                                            tmsg, nullptr, trir, TT,
                                                            TT, DD, DD, DD, DD);
        scatter_kernel<<<18750, blk>>>(tmsg, trir, nmsg, cnt);
        u_kernel<<<(unsigned)(ND / 256), blk>>>(nmsg, cnt, u);
        gemm_cp<0, 0, 0><<<dim3(782, 2), blk, GEMM_SMEM>>>(u, gateW_rt + DD, glog2, nullptr,
                                                           nullptr, 0, NN, DD, DD, 2 * DD, DD);
        h_kernel<<<(unsigned)(ND / 256), blk>>>(u, glog1, glog2, xres, src + (size_t)r * ND);
    }

    gemm_cp<0, 0, 0><<<dim3(3125, 6), blk, GEMM_SMEM>>>(src, inW_rt, qkv, inB, nullptr, 0,
                                                        RR * NN, DD, DD, DD, 3 * DD);
    attn_kernel<<<25000, blk>>>(qkv, oattn);
    gemm_cp<0, 0, 0><<<dim3(3125, 2), blk, GEMM_SMEM>>>(oattn, outW_rt, oproj, outB,
                                                        nullptr, 0, RR * NN, DD, DD, DD, DD);
    ln_add_kernel<<<50000, blk>>>(src, oproj, ln1g, ln1b, x1, (size_t)RR * NN);
    gemm_cp<0, 1, 1><<<dim3(3125, 4), blk, GEMM_SMEM>>>(x1, lin1W_rt, ff1, lin1b, nullptr, 0,
                                                        RR * NN, DD, DD, DD, 2 * DD);
    gemm_cp<0, 0, 0><<<dim3(3125, 2), blk, GEMM_SMEM>>>(ff1, lin2W_rt, ff2, lin2b, nullptr, 0,
                                                        RR * NN, 2 * DD, 2 * DD, 2 * DD, DD);
    final_kernel<<<12500, blk>>>(x1, ff2, ln2g, ln2b, out);
}

// round 8
// speedup vs baseline: 3.3759x; 1.3315x over previous
#include <cuda_runtime.h>
#include <cuda_fp16.h>
#include <math.h>
#include <stddef.h>
#include <stdint.h>

#define NN 100000
#define DD 256
#define RR 4
#define TT 150000
#define HH 2

constexpr size_t ND  = (size_t)NN * DD;         // 25.6M floats
constexpr size_t RND = (size_t)RR * NN * DD;    // 102.4M floats

__device__ float  g_arena[5 * RND];
__device__ __half g_combh[(size_t)RR * DD * DD];
// half weights: resW | gateW | inW | outW | lin1W | lin2W
__device__ __half g_wh[65536 + 131072 + 196608 + 65536 + 131072 + 131072];

// ---------------- helpers ----------------------------------------------------
__device__ __forceinline__ float warp_sum(float v) {
#pragma unroll
    for (int o = 16; o; o >>= 1) v += __shfl_xor_sync(0xffffffffu, v, o);
    return v;
}
__device__ __forceinline__ float gelu_exact(float x) {
    return 0.5f * x * (1.0f + erff(x * 0.7071067811865475f));
}
__device__ __forceinline__ uint32_t sm2u32(const void* p) {
    uint32_t a;
    asm("{ .reg .u64 t; cvta.to.shared.u64 t, %1; cvt.u32.u64 %0, t; }"
        : "=r"(a) : "l"(p));
    return a;
}
__device__ __forceinline__ void mma_f16(float& c0, float& c1, float& c2, float& c3,
                                        uint32_t a0, uint32_t a1, uint32_t a2, uint32_t a3,
                                        uint32_t b0, uint32_t b1) {
    asm volatile(
        "mma.sync.aligned.m16n8k16.row.col.f32.f16.f16.f32 "
        "{%0,%1,%2,%3}, {%4,%5,%6,%7}, {%8,%9}, {%0,%1,%2,%3};"
        : "+f"(c0), "+f"(c1), "+f"(c2), "+f"(c3)
        : "r"(a0), "r"(a1), "r"(a2), "r"(a3), "r"(b0), "r"(b1));
}
__device__ __forceinline__ void cp16(uint32_t dst, const void* src, uint32_t sz) {
    asm volatile("cp.async.cg.shared.global [%0], [%1], 16, %2;"
                 :: "r"(dst), "l"(src), "r"(sz) : "memory");
}

// ---------------- FP16 GEMM: C[M,Nc] = A[M,K] @ B[Nc,K]^T (fp32 accum) -------
// 4-stage cp.async pipeline. 80B-pitch rows (40 halves) -> bank-disjoint LDS.
// TRIA: A rows = mean of 3 gathered x_h rows. ACT: GELU. HOUT: store half.
#define BM 128
#define BN 128
#define BKH 32                        /* k per tile (halves) */
#define PITCH_H 40                    /* halves per row (80B) */
#define NSTG 4
#define A_BY (BM * PITCH_H * 2)       /* 10240 B */
#define STG_BY (2 * A_BY)             /* 20480 B */
#define GEMM_SMEM (NSTG * STG_BY)     /* 80 KB */

template <int TRIA, int ACT, int HOUT>
__global__ __launch_bounds__(256, 2)
void gemm_h(const __half* __restrict__ A, const __half* __restrict__ B,
            void* __restrict__ Cv, const float* __restrict__ bias,
            const int* __restrict__ tri, int triN,
            int M, int K, int lda, int ldb, int ldc)
{
    extern __shared__ uint32_t smw[];
    const int tid  = threadIdx.x;
    const int m0   = blockIdx.x * BM;
    const int n0   = blockIdx.y * BN;
    const int w    = tid >> 5, lane = tid & 31;
    const int wm   = w >> 2;           // 2 warps along M (64 rows)
    const int wn   = w & 3;            // 4 warps along N (32 cols)
    const int g    = lane >> 2;
    const int c4   = lane & 3;
    const uint32_t sbase = sm2u32(smw);

    // producer: one row per thread, two 16B granules (8 halves each)
    const int prow  = tid >> 1;
    const int pkq0  = (tid & 1) * 16;    // halves
    const int grA   = m0 + prow;
    int ti0 = 0, ti1 = 0, ti2 = 0;
    if (TRIA) {
        int s = (grA < M) ? grA : 0;
        ti0 = tri[s]; ti1 = tri[triN + s]; ti2 = tri[2 * triN + s];
    }

    float acc[4][4][4];
#pragma unroll
    for (int i = 0; i < 4; i++)
#pragma unroll
        for (int j = 0; j < 4; j++)
#pragma unroll
            for (int e = 0; e < 4; e++) acc[i][j][e] = 0.f;

    auto tria_ldg = [&](int i, int kk) -> uint4 {
        const int kq = pkq0 + i * 8;
        const uint4 q0 = *(const uint4*)(A + (size_t)ti0 * lda + kk + kq);
        const uint4 q1 = *(const uint4*)(A + (size_t)ti1 * lda + kk + kq);
        const uint4 q2 = *(const uint4*)(A + (size_t)ti2 * lda + kk + kq);
        uint4 r;
        const float th = 1.f / 3.f;
#pragma unroll
        for (int j = 0; j < 4; j++) {
            float2 f0 = __half22float2(((const __half2*)&q0)[j]);
            float2 f1 = __half22float2(((const __half2*)&q1)[j]);
            float2 f2 = __half22float2(((const __half2*)&q2)[j]);
            ((__half2*)&r)[j] = __floats2half2_rn((f0.x + f1.x + f2.x) * th,
                                                  (f0.y + f1.y + f2.y) * th);
        }
        return r;
    };
    auto sts_a = [&](int st, int i, uint4 v) {
        uint32_t dst = sbase + st * STG_BY + prow * 80 + (pkq0 + i * 8) * 2;
        asm volatile("st.shared.v4.b32 [%0], {%1,%2,%3,%4};"
                     :: "r"(dst), "r"(v.x), "r"(v.y), "r"(v.z), "r"(v.w) : "memory");
    };
    auto issue_tile = [&](int ct) {
        const int st = ct & (NSTG - 1);
        const uint32_t sb = sbase + st * STG_BY;
        const int kk = ct * BKH;
#pragma unroll
        for (int i = 0; i < 2; i++) {
            const int kq = pkq0 + i * 8;
            const uint32_t doff = prow * 80 + kq * 2;
            if (!TRIA) {
                const __half* sa = A + (size_t)((grA < M) ? grA : 0) * lda + kk + kq;
                cp16(sb + doff, sa, (grA < M) ? 16u : 0u);
            }
            const __half* sbp = B + (size_t)(n0 + prow) * ldb + kk + kq;
            cp16(sb + A_BY + doff, sbp, 16u);
        }
    };

    const int nt = K / BKH;
    // ---- prologue: stages 0..NSTG-2 ----
#pragma unroll
    for (int ct = 0; ct < NSTG - 1; ct++) {
        if (TRIA) { sts_a(ct, 0, tria_ldg(0, ct * BKH)); sts_a(ct, 1, tria_ldg(1, ct * BKH)); }
        issue_tile(ct);
        asm volatile("cp.async.commit_group;" ::: "memory");
    }

    for (int c = 0; c < nt; c++) {
        const int st = c & (NSTG - 1);
        uint4 tv0, tv1;
        const bool more = (c + NSTG - 1) < nt;
        if (TRIA && more) {
            tv0 = tria_ldg(0, (c + NSTG - 1) * BKH);
            tv1 = tria_ldg(1, (c + NSTG - 1) * BKH);
        }
        asm volatile("cp.async.wait_group %0;" :: "n"(NSTG - 2) : "memory");
        __syncthreads();
        if (more) {
            const int wst = (c + NSTG - 1) & (NSTG - 1);
            if (TRIA) { sts_a(wst, 0, tv0); sts_a(wst, 1, tv1); }
            issue_tile(c + NSTG - 1);
        }
        asm volatile("cp.async.commit_group;" ::: "memory");

        const uint32_t* sA = smw + st * (STG_BY / 4);
        const uint32_t* sB = sA + (A_BY / 4);
#pragma unroll
        for (int kb2 = 0; kb2 < 16; kb2 += 8) {        // two k16 steps
            uint32_t af[4][4];
#pragma unroll
            for (int mf = 0; mf < 4; mf++) {
                const int mi = (wm * 64 + mf * 16 + g) * 20 + kb2 + c4;
                af[mf][0] = sA[mi];        af[mf][1] = sA[mi + 160];
                af[mf][2] = sA[mi + 4];    af[mf][3] = sA[mi + 164];
            }
#pragma unroll
            for (int nf = 0; nf < 4; nf++) {
                const int ni = (wn * 32 + nf * 8 + g) * 20 + kb2 + c4;
                const uint32_t b0 = sB[ni];
                const uint32_t b1 = sB[ni + 4];
#pragma unroll
                for (int mf = 0; mf < 4; mf++)
                    mma_f16(acc[mf][nf][0], acc[mf][nf][1], acc[mf][nf][2], acc[mf][nf][3],
                            af[mf][0], af[mf][1], af[mf][2], af[mf][3], b0, b1);
            }
        }
    }

    // --- epilogue ---
    const bool hb = (bias != nullptr);
#pragma unroll
    for (int mf = 0; mf < 4; mf++) {
#pragma unroll
        for (int half = 0; half < 2; half++) {
            int gm = m0 + wm * 64 + mf * 16 + g + half * 8;
            if (gm >= M) continue;
#pragma unroll
            for (int nf = 0; nf < 4; nf++) {
                int col = wn * 32 + nf * 8 + c4 * 2;
                float v0 = acc[mf][nf][half * 2 + 0];
                float v1 = acc[mf][nf][half * 2 + 1];
                if (hb) { v0 += bias[n0 + col]; v1 += bias[n0 + col + 1]; }
                if (ACT == 1) { v0 = gelu_exact(v0); v1 = gelu_exact(v1); }
                if (HOUT) {
                    __half* cp = (__half*)Cv + (size_t)gm * ldc + n0 + col;
                    *(__half2*)cp = __floats2half2_rn(v0, v1);
                } else {
                    float* cp = (float*)Cv + (size_t)gm * ldc + n0 + col;
                    *(float2*)cp = make_float2(v0, v1);
                }
            }
        }
    }
}

// ---------------- comb[r] = half(tri_W[r] @ node_W[r]) -----------------------
__global__ void combw_kernel(const float* __restrict__ nodeW,
                             const float* __restrict__ triW,
                             __half* __restrict__ comb)
{
    __shared__ float Ts[16][16];
    __shared__ float Ns[16][17];
    int r  = blockIdx.z;
    int ii = blockIdx.y * 16 + threadIdx.y;
    int kk = blockIdx.x * 16 + threadIdx.x;
    const float* tw = triW  + (size_t)r * DD * DD;
    const float* nw = nodeW + (size_t)r * DD * DD;
    float s = 0.f;
    for (int j0 = 0; j0 < DD; j0 += 16) {
        Ts[threadIdx.y][threadIdx.x] = tw[(size_t)ii * DD + j0 + threadIdx.x];
        Ns[threadIdx.y][threadIdx.x] = nw[(size_t)(j0 + threadIdx.y) * DD + kk];
        __syncthreads();
#pragma unroll
        for (int j = 0; j < 16; j++) s = fmaf(Ts[threadIdx.y][j], Ns[j][threadIdx.x], s);
        __syncthreads();
    }
    comb[((size_t)r * DD + ii) * DD + kk] = __float2half_rn(s);
}

// ---------------- fp32 -> fp16 copy -------------------------------------------
__global__ void tohalf_kernel(const float* __restrict__ src, __half* __restrict__ dst,
                              size_t n) {
    size_t i = (size_t)blockIdx.x * blockDim.x + threadIdx.x;
    if (i < n) dst[i] = __float2half_rn(src[i]);
}

// ---------------- misc elementwise kernels -----------------------------------
__global__ void scatter_kernel(const float* __restrict__ tmsg,
                               const int* __restrict__ tri,
                               float* __restrict__ nmsg, float* __restrict__ cnt)
{
    int gw   = (int)(((size_t)blockIdx.x * blockDim.x + threadIdx.x) >> 5);
    int lane = threadIdx.x & 31;
    if (gw >= TT) return;
    int t0 = tri[gw], t1 = tri[TT + gw], t2 = tri[2 * TT + gw];
    const float* row = tmsg + (size_t)gw * DD;
    float v[8];
#pragma unroll
    for (int e = 0; e < 8; e++) v[e] = row[lane + 32 * e];
    float* p0 = nmsg + (size_t)t0 * DD;
    float* p1 = nmsg + (size_t)t1 * DD;
    float* p2 = nmsg + (size_t)t2 * DD;
#pragma unroll
    for (int e = 0; e < 8; e++) {
        int d = lane + 32 * e;
        atomicAdd(p0 + d, v[e]);
        atomicAdd(p1 + d, v[e]);
        atomicAdd(p2 + d, v[e]);
    }
    if (lane == 0) {
        atomicAdd(cnt + t0, 1.f);
        atomicAdd(cnt + t1, 1.f);
        atomicAdd(cnt + t2, 1.f);
    }
}

__global__ void u_kernel(const float* __restrict__ nmsg,
                         const float* __restrict__ cnt, __half* __restrict__ u)
{
    size_t i = (size_t)blockIdx.x * blockDim.x + threadIdx.x;
    if (i >= ND) return;
    int n = (int)(i >> 8);
    float c = fmaxf(cnt[n], 1.f);
    float v = nmsg[i] / c;
    u[i] = __float2half_rn(v > 0.f ? v : expm1f(v));    // ELU(alpha=1)
}

__global__ void h_kernel(const __half* __restrict__ u,
                         const float* __restrict__ glog1, const float* __restrict__ glog2,
                         const float* __restrict__ xres,
                         float* __restrict__ dst, __half* __restrict__ dsth)
{
    size_t i = (size_t)blockIdx.x * blockDim.x + threadIdx.x;
    if (i >= ND) return;
    float a = 1.f / (1.f + expf(-(glog1[i] + glog2[i])));
    float v = tanhf(__half2float(u[i])) * a + xres[i] * (1.f - a);
    dst[i]  = v;
    dsth[i] = __float2half_rn(v);
}

// ---------------- attention over relation axis (R=4): warp per (node, head) --
__global__ void attn_kernel(const float* __restrict__ qkv, __half* __restrict__ oat)
{
    size_t gt = (size_t)blockIdx.x * blockDim.x + threadIdx.x;
    int gw   = (int)(gt >> 5);
    int lane = threadIdx.x & 31;
    if (gw >= NN * HH) return;
    int n = gw >> 1, h = gw & 1;

    float q[4][4], k[4][4], v[4][4];
#pragma unroll
    for (int r = 0; r < RR; r++) {
        const float* base = qkv + ((size_t)r * NN + n) * (3 * DD) + h * 128 + lane;
#pragma unroll
        for (int e = 0; e < 4; e++) {
            q[r][e] = base[32 * e];
            k[r][e] = base[256 + 32 * e];
            v[r][e] = base[512 + 32 * e];
        }
    }
    float s[4][4];
#pragma unroll
    for (int a = 0; a < 4; a++)
#pragma unroll
        for (int b = 0; b < 4; b++) {
            float p = 0.f;
#pragma unroll
            for (int e = 0; e < 4; e++) p = fmaf(q[a][e], k[b][e], p);
            s[a][b] = warp_sum(p) * 0.08838834764831845f;  // 1/sqrt(128)
        }
    float o[4][4];
#pragma unroll
    for (int a = 0; a < 4; a++)
#pragma unroll
        for (int e = 0; e < 4; e++) o[a][e] = 0.f;
#pragma unroll
    for (int a = 0; a < 4; a++) {
        float m = fmaxf(fmaxf(s[a][0], s[a][1]), fmaxf(s[a][2], s[a][3]));
        float p[4]; float sum = 0.f;
#pragma unroll
        for (int b = 0; b < 4; b++) { p[b] = expf(s[a][b] - m); sum += p[b]; }
        float inv = 1.f / sum;
#pragma unroll
        for (int b = 0; b < 4; b++) {
            float wgt = p[b] * inv;
#pragma unroll
            for (int e = 0; e < 4; e++) o[a][e] = fmaf(wgt, v[b][e], o[a][e]);
        }
    }
#pragma unroll
    for (int a = 0; a < 4; a++) {
        __half* dst = oat + ((size_t)a * NN + n) * DD + h * 128 + lane;
#pragma unroll
        for (int e = 0; e < 4; e++) dst[32 * e] = __float2half_rn(o[a][e]);
    }
}

// ---------------- LayerNorm(A+B): fp32 out + half out ------------------------
__global__ void ln_add_kernel(const float* __restrict__ A, const float* __restrict__ Bv,
                              const float* __restrict__ g, const float* __restrict__ bb,
                              float* __restrict__ out, __half* __restrict__ outh,
                              size_t rows)
{
    size_t gt = (size_t)blockIdx.x * blockDim.x + threadIdx.x;
    size_t w  = gt >> 5;
    int lane  = threadIdx.x & 31;
    if (w >= rows) return;
    const float* pa = A + w * DD;
    const float* pb = Bv + w * DD;
    float y[8]; float s = 0.f;
#pragma unroll
    for (int e = 0; e < 8; e++) { int d = lane + 32 * e; y[e] = pa[d] + pb[d]; s += y[e]; }
    s = warp_sum(s);
    float mean = s * (1.f / DD);
    float vs = 0.f;
#pragma unroll
    for (int e = 0; e < 8; e++) { float dv = y[e] - mean; vs += dv * dv; }
    vs = warp_sum(vs);
    float inv = rsqrtf(vs * (1.f / DD) + 1e-5f);
    float*  po = out  + w * DD;
    __half* ph = outh + w * DD;
#pragma unroll
    for (int e = 0; e < 8; e++) {
        int d = lane + 32 * e;
        float v = (y[e] - mean) * inv * g[d] + bb[d];
        po[d] = v;
        ph[d] = __float2half_rn(v);
    }
}

// ---------------- final: mean over R of LN(x1+ff2), warp per node ------------
__global__ void final_kernel(const float* __restrict__ x1, const float* __restrict__ ff2,
                             const float* __restrict__ g, const float* __restrict__ bb,
                             float* __restrict__ out)
{
    size_t gt = (size_t)blockIdx.x * blockDim.x + threadIdx.x;
    size_t n  = gt >> 5;
    int lane  = threadIdx.x & 31;
    if (n >= NN) return;
    float acc[8];
#pragma unroll
    for (int e = 0; e < 8; e++) acc[e] = 0.f;
    for (int r = 0; r < RR; r++) {
        size_t off = ((size_t)r * NN + n) * DD;
        float y[8]; float s = 0.f;
#pragma unroll
        for (int e = 0; e < 8; e++) {
            int d = lane + 32 * e;
            y[e] = x1[off + d] + ff2[off + d];
            s += y[e];
        }
        s = warp_sum(s);
        float mean = s * (1.f / DD);
        float vs = 0.f;
#pragma unroll
        for (int e = 0; e < 8; e++) { float dv = y[e] - mean; vs += dv * dv; }
        vs = warp_sum(vs);
        float inv = rsqrtf(vs * (1.f / DD) + 1e-5f);
#pragma unroll
        for (int e = 0; e < 8; e++) {
            int d = lane + 32 * e;
            acc[e] += (y[e] - mean) * inv * g[d] + bb[d];
        }
    }
#pragma unroll
    for (int e = 0; e < 8; e++) out[n * DD + lane + 32 * e] = acc[e] * 0.25f;
}

// ---------------- launch ------------------------------------------------------
extern "C" void kernel_launch(void* const* d_in, const int* in_sizes, int n_in,
                              void* d_out, int out_size)
{
    const float* x     = (const float*)d_in[0];
    const int*   tris  = (const int*)  d_in[1];
    // d_in[2] = edge_index (unused)
    const float* nodeW = (const float*)d_in[3];
    const float* triW  = (const float*)d_in[4];
    const float* resW  = (const float*)d_in[5];
    const float* gateW = (const float*)d_in[6];
    const float* gateB = (const float*)d_in[7];
    const float* inW   = (const float*)d_in[8];
    const float* inB   = (const float*)d_in[9];
    const float* outW  = (const float*)d_in[10];
    const float* outB  = (const float*)d_in[11];
    const float* ln1g  = (const float*)d_in[12];
    const float* ln1b  = (const float*)d_in[13];
    const float* lin1W = (const float*)d_in[14];
    const float* lin1b = (const float*)d_in[15];
    const float* lin2W = (const float*)d_in[16];
    const float* lin2b = (const float*)d_in[17];
    const float* ln2g  = (const float*)d_in[18];
    const float* ln2b  = (const float*)d_in[19];
    float* out = (float*)d_out;

    float* arena;
    __half *combh, *wh;
    cudaGetSymbolAddress((void**)&arena, g_arena);
    cudaGetSymbolAddress((void**)&combh, g_combh);
    cudaGetSymbolAddress((void**)&wh,    g_wh);

    // ---- aliased buffer map ----
    float* src   = arena;                       // RND fp32 (residual; later x1)
    float* big   = arena + RND;                 // 12*ND floats
    float* t2    = arena + 4 * RND;             // RND floats
    // phase A (inside big):
    float*  xres  = big;                        // ND
    float*  glog1 = big + ND;                   // ND
    float*  glog2 = big + 2 * ND;               // ND
    float*  nmsg  = big + 3 * ND;               // ND
    float*  tmsg  = big + 4 * ND;               // 1.5*ND
    float*  cnt   = big + 11 * ND / 2;          // NN
    __half* u_h   = (__half*)(big + 6 * ND);    // ND halves
    __half* x_h   = (__half*)(big + 13 * ND / 2); // ND halves
    // phase B:
    float*  qkv    = big;                       // 3*RND fp32
    __half* src_h  = (__half*)t2;               // RND halves
    __half* oat_h  = (__half*)(t2 + RND / 2);   // RND halves
    float*  oproj  = big;                       // RND fp32 (qkv dead)
    float*  x1     = src;                       // in-place
    __half* x1_h   = (__half*)t2;               // RND halves (src_h dead)
    __half* ff1_h  = (__half*)big;              // 2*RND halves (oproj dead)
    float*  ff2    = big + RND;                 // RND fp32 (after ff1 region)
    // half weights
    __half* resW_h  = wh;
    __half* gateW_h = wh + 65536;
    __half* inW_h   = gateW_h + 131072;
    __half* outW_h  = inW_h + 196608;
    __half* lin1W_h = outW_h + 65536;
    __half* lin2W_h = lin1W_h + 131072;

    cudaFuncSetAttribute(gemm_h<0, 0, 0>, cudaFuncAttributeMaxDynamicSharedMemorySize, GEMM_SMEM);
    cudaFuncSetAttribute(gemm_h<1, 0, 0>, cudaFuncAttributeMaxDynamicSharedMemorySize, GEMM_SMEM);
    cudaFuncSetAttribute(gemm_h<0, 1, 1>, cudaFuncAttributeMaxDynamicSharedMemorySize, GEMM_SMEM);

    dim3 blk(256);

    // operand conversions
    tohalf_kernel<<<(unsigned)((ND + 255) / 256), blk>>>(x, x_h, ND);
    tohalf_kernel<<<256, blk>>>(resW,  resW_h,  65536);
    tohalf_kernel<<<512, blk>>>(gateW, gateW_h, 131072);
    tohalf_kernel<<<768, blk>>>(inW,   inW_h,   196608);
    tohalf_kernel<<<256, blk>>>(outW,  outW_h,  65536);
    tohalf_kernel<<<512, blk>>>(lin1W, lin1W_h, 131072);
    tohalf_kernel<<<512, blk>>>(lin2W, lin2W_h, 131072);
    combw_kernel<<<dim3(16, 16, RR), dim3(16, 16)>>>(nodeW, triW, combh);

    gemm_h<0, 0, 0><<<dim3(782, 2), blk, GEMM_SMEM>>>(x_h, resW_h, xres, nullptr,
                                                      nullptr, 0, NN, DD, DD, DD, DD);
    gemm_h<0, 0, 0><<<dim3(782, 2), blk, GEMM_SMEM>>>(x_h, gateW_h, glog1, gateB,
                                                      nullptr, 0, NN, DD, DD, 2 * DD, DD);

    for (int r = 0; r < RR; r++) {
        const int* trir = tris + (size_t)r * 3 * TT;
        cudaMemsetAsync(nmsg, 0, ND * sizeof(float), 0);
        cudaMemsetAsync(cnt, 0, (size_t)NN * sizeof(float), 0);
        gemm_h<1, 0, 0><<<dim3(1172, 2), blk, GEMM_SMEM>>>(x_h, combh + (size_t)r * DD * DD,
                                                           tmsg, nullptr, trir, TT,
                                                           TT, DD, DD, DD, DD);
        scatter_kernel<<<18750, blk>>>(tmsg, trir, nmsg, cnt);
        u_kernel<<<(unsigned)(ND / 256), blk>>>(nmsg, cnt, u_h);
        gemm_h<0, 0, 0><<<dim3(782, 2), blk, GEMM_SMEM>>>(u_h, gateW_h + DD, glog2, nullptr,
                                                          nullptr, 0, NN, DD, DD, 2 * DD, DD);
        h_kernel<<<(unsigned)(ND / 256), blk>>>(u_h, glog1, glog2, xres,
                                                src + (size_t)r * ND,
                                                src_h + (size_t)r * ND);
    }

    gemm_h<0, 0, 0><<<dim3(3125, 6), blk, GEMM_SMEM>>>(src_h, inW_h, qkv, inB, nullptr, 0,
                                                       RR * NN, DD, DD, DD, 3 * DD);
    attn_kernel<<<25000, blk>>>(qkv, oat_h);
    gemm_h<0, 0, 0><<<dim3(3125, 2), blk, GEMM_SMEM>>>(oat_h, outW_h, oproj, outB,
                                                       nullptr, 0, RR * NN, DD, DD, DD, DD);
    ln_add_kernel<<<50000, blk>>>(src, oproj, ln1g, ln1b, x1, x1_h, (size_t)RR * NN);
    gemm_h<0, 1, 1><<<dim3(3125, 4), blk, GEMM_SMEM>>>(x1_h, lin1W_h, ff1_h, lin1b, nullptr, 0,
                                                       RR * NN, DD, DD, DD, 2 * DD);
    gemm_h<0, 0, 0><<<dim3(3125, 2), blk, GEMM_SMEM>>>(ff1_h, lin2W_h, ff2, lin2b, nullptr, 0,
                                                       RR * NN, 2 * DD, 2 * DD, 2 * DD, DD);
    final_kernel<<<12500, blk>>>(x1, ff2, ln2g, ln2b, out);
}